// round 13
// baseline (speedup 1.0000x reference)
#include <cuda_runtime.h>
#include <cuda_bf16.h>
#include <cstdint>
#include <math.h>

#define BB 2
#define SS 2048
#define DD 1024
#define HH 16
#define DK 64
#define NT (BB*SS)   // 4096 tokens

typedef __nv_bfloat16 bf16;

// ---- scratch (static device globals; no allocations) ----
__device__ bf16 g_aqh[(size_t)NT*DD], g_aql[(size_t)NT*DD];
__device__ bf16 g_akh[(size_t)NT*DD], g_akl[(size_t)NT*DD];
__device__ bf16 g_avh[(size_t)NT*DD], g_avl[(size_t)NT*DD];
__device__ bf16 g_wqh[(size_t)DD*DD], g_wql[(size_t)DD*DD];
__device__ bf16 g_wkh[(size_t)DD*DD], g_wkl[(size_t)DD*DD];
__device__ bf16 g_wvh[(size_t)DD*DD], g_wvl[(size_t)DD*DD];
__device__ bf16 g_wfh[(size_t)DD*DD], g_wfl[(size_t)DD*DD];
__device__ bf16 g_qh[(size_t)NT*DD], g_ql[(size_t)NT*DD];
__device__ bf16 g_kh[(size_t)NT*DD], g_kl[(size_t)NT*DD];
__device__ bf16 g_vh[(size_t)NT*DD], g_vl[(size_t)NT*DD];
__device__ bf16 g_ch[(size_t)NT*DD], g_cl[(size_t)NT*DD];
__device__ float g_pre[(size_t)NT*DD];
__device__ float g_scores[(size_t)BB*HH*SS*SS];   // fallback attn target only
__device__ float g_dummy_out[(size_t)NT*DD];
__device__ float g_ls[(size_t)32*SS];             // row sums

// ============================================================
// warp-MMA helpers (baseline PTX: sm_80+, no 'a' features)
// ============================================================
__device__ __forceinline__ uint32_t smem_u32(const void* p) {
    uint32_t a;
    asm("{ .reg .u64 t; cvta.to.shared.u64 t, %1; cvt.u32.u64 %0, t; }"
        : "=r"(a) : "l"(p));
    return a;
}
__device__ __forceinline__ void ldsm_x4(uint32_t* r, uint32_t addr) {
    asm volatile("ldmatrix.sync.aligned.m8n8.x4.shared.b16 {%0,%1,%2,%3}, [%4];"
        : "=r"(r[0]), "=r"(r[1]), "=r"(r[2]), "=r"(r[3]) : "r"(addr));
}
__device__ __forceinline__ void ldsm_x4_t(uint32_t* r, uint32_t addr) {
    asm volatile("ldmatrix.sync.aligned.m8n8.x4.trans.shared.b16 {%0,%1,%2,%3}, [%4];"
        : "=r"(r[0]), "=r"(r[1]), "=r"(r[2]), "=r"(r[3]) : "r"(addr));
}
__device__ __forceinline__ void mma_bf16(float* c, const uint32_t* a, const uint32_t* b) {
    asm volatile(
        "mma.sync.aligned.m16n8k16.row.col.f32.bf16.bf16.f32 "
        "{%0,%1,%2,%3}, {%4,%5,%6,%7}, {%8,%9}, {%0,%1,%2,%3};"
        : "+f"(c[0]), "+f"(c[1]), "+f"(c[2]), "+f"(c[3])
        : "r"(a[0]), "r"(a[1]), "r"(a[2]), "r"(a[3]), "r"(b[0]), "r"(b[1]));
}
__device__ __forceinline__ uint32_t packhl(float a, float b, uint32_t& lo) {
    __nv_bfloat162 hb = __float22bfloat162_rn(make_float2(a, b));
    float2 hf = __bfloat1622float2(hb);
    __nv_bfloat162 lb = __float22bfloat162_rn(make_float2(a - hf.x, b - hf.y));
    lo = *(uint32_t*)&lb;
    return *(uint32_t*)&hb;
}
__device__ __forceinline__ void stg_cs_f2(float* p, float x, float y) {
    asm volatile("st.global.cs.v2.f32 [%0], {%1,%2};" :: "l"(p), "f"(x), "f"(y));
}

// ============================================================
// pre-split: fp32 tensor -> bf16 hi/lo
// ============================================================
__global__ void presplit(const float4* __restrict__ x,
                         uint2* __restrict__ hi, uint2* __restrict__ lo)
{
    const int i = blockIdx.x*blockDim.x + threadIdx.x;
    float4 v = x[i];
    __nv_bfloat162 h01 = __float22bfloat162_rn(make_float2(v.x, v.y));
    __nv_bfloat162 h23 = __float22bfloat162_rn(make_float2(v.z, v.w));
    float2 f01 = __bfloat1622float2(h01);
    float2 f23 = __bfloat1622float2(h23);
    __nv_bfloat162 l01 = __float22bfloat162_rn(make_float2(v.x - f01.x, v.y - f01.y));
    __nv_bfloat162 l23 = __float22bfloat162_rn(make_float2(v.z - f23.x, v.w - f23.y));
    hi[i] = make_uint2(*(uint32_t*)&h01, *(uint32_t*)&h23);
    lo[i] = make_uint2(*(uint32_t*)&l01, *(uint32_t*)&l23);
}

// smem tile layout for gemm (per buffer): Ah,Al,Bh,Bl each 128 rows x 48 bytes
#define T_AH 0
#define T_AL 6144
#define T_BH 12288
#define T_BL 18432
#define BUFB 24576
#define DYNSM (2*BUFB)   // 48KB

__device__ __forceinline__ void mma_pass(float acc[2][8][4],
                                         uint32_t Af[2][4], uint32_t Bf[4][4])
{
#pragma unroll
    for (int ti = 0; ti < 2; ti++)
#pragma unroll
        for (int tj = 0; tj < 8; tj++)
            mma_bf16(acc[ti][tj], Af[ti], &Bf[tj >> 1][(tj & 1) * 2]);
}

// gemm core body: C = A @ B^T on pre-split bf16
__device__ __forceinline__ void gemm_body(
    const bf16* __restrict__ Ah, const bf16* __restrict__ Al,
    const bf16* __restrict__ Bh, const bf16* __restrict__ Bl,
    float* __restrict__ Cf, bf16* __restrict__ Ch, bf16* __restrict__ Cl,
    int N, int K, char* sm)
{
    const uint32_t smb = smem_u32(sm);
    const int t = threadIdx.x;
    const int lane = t & 31, warp = t >> 5;
    const int wm = warp >> 1, wn = warp & 1;
    const int i0 = blockIdx.y * 128, j0 = blockIdx.x * 128;

    float acc[2][8][4];
#pragma unroll
    for (int a = 0; a < 2; a++)
#pragma unroll
        for (int b = 0; b < 8; b++)
#pragma unroll
            for (int c = 0; c < 4; c++) acc[a][b][c] = 0.f;

    const int r = t >> 1, kc = (t & 1) * 8;
    const int stoff = r * 48 + (t & 1) * 16;
    const bf16* pAh = Ah + (size_t)(i0 + r) * K + kc;
    const bf16* pAl = Al + (size_t)(i0 + r) * K + kc;
    const bf16* pBh = Bh + (size_t)(j0 + r) * K + kc;
    const bf16* pBl = Bl + (size_t)(j0 + r) * K + kc;

    const uint32_t a_off = (uint32_t)((wm*32 + (lane & 15)) * 48 + ((lane >> 4) & 1) * 16);
    const uint32_t b_off = (uint32_t)((wn*64 + (lane & 7) + ((lane >> 4) & 1) * 8) * 48
                                      + ((lane >> 3) & 1) * 16);

    *(uint4*)(sm + T_AH + stoff) = *(const uint4*)pAh;
    *(uint4*)(sm + T_AL + stoff) = *(const uint4*)pAl;
    *(uint4*)(sm + T_BH + stoff) = *(const uint4*)pBh;
    *(uint4*)(sm + T_BL + stoff) = *(const uint4*)pBl;
    __syncthreads();

    const int nst = K / 16;
    for (int s = 0; s < nst; s++) {
        const int buf = (s & 1) * BUFB;
        const bool more = (s + 1 < nst);
        uint4 nA, nAl, nB, nBl;
        if (more) {
            nA  = *(const uint4*)(pAh + (s+1)*16);
            nAl = *(const uint4*)(pAl + (s+1)*16);
            nB  = *(const uint4*)(pBh + (s+1)*16);
            nBl = *(const uint4*)(pBl + (s+1)*16);
        }
        uint32_t Af[2][4], Bf[4][4], X[4][4];
#pragma unroll
        for (int ti = 0; ti < 2; ti++)
            ldsm_x4(Af[ti], smb + buf + T_AH + a_off + ti*16*48);
#pragma unroll
        for (int pj = 0; pj < 4; pj++)
            ldsm_x4(Bf[pj], smb + buf + T_BH + b_off + pj*16*48);
        mma_pass(acc, Af, Bf);
#pragma unroll
        for (int pj = 0; pj < 4; pj++)
            ldsm_x4(X[pj], smb + buf + T_BL + b_off + pj*16*48);
        mma_pass(acc, Af, X);
#pragma unroll
        for (int ti = 0; ti < 2; ti++)
            ldsm_x4(X[ti], smb + buf + T_AL + a_off + ti*16*48);
        mma_pass(acc, X, Bf);

        if (more) {
            __syncthreads();
            const int nb = buf ^ BUFB;
            *(uint4*)(sm + nb + T_AH + stoff) = nA;
            *(uint4*)(sm + nb + T_AL + stoff) = nAl;
            *(uint4*)(sm + nb + T_BH + stoff) = nB;
            *(uint4*)(sm + nb + T_BL + stoff) = nBl;
            __syncthreads();
        }
    }

    const int rb = i0 + wm*32 + (lane >> 2);
    const int cb = j0 + wn*64 + (lane & 3) * 2;
    if (Cf) {
#pragma unroll
        for (int ti = 0; ti < 2; ti++)
#pragma unroll
            for (int tj = 0; tj < 8; tj++) {
                const int i = rb + ti*16, j = cb + tj*8;
                *(float2*)&Cf[(size_t)i*N + j]     = make_float2(acc[ti][tj][0], acc[ti][tj][1]);
                *(float2*)&Cf[(size_t)(i+8)*N + j] = make_float2(acc[ti][tj][2], acc[ti][tj][3]);
            }
    } else {
#pragma unroll
        for (int ti = 0; ti < 2; ti++)
#pragma unroll
            for (int tj = 0; tj < 8; tj++) {
                const int i = rb + ti*16, j = cb + tj*8;
                uint32_t lo0, lo1;
                uint32_t hi0 = packhl(acc[ti][tj][0], acc[ti][tj][1], lo0);
                uint32_t hi1 = packhl(acc[ti][tj][2], acc[ti][tj][3], lo1);
                *(uint32_t*)&Ch[(size_t)i*N + j]     = hi0;
                *(uint32_t*)&Cl[(size_t)i*N + j]     = lo0;
                *(uint32_t*)&Ch[(size_t)(i+8)*N + j] = hi1;
                *(uint32_t*)&Cl[(size_t)(i+8)*N + j] = lo1;
            }
    }
}

// fused QKV projections: blockIdx.z selects operand set
__global__ __launch_bounds__(256, 2)
void gemm_qkv(void)
{
    extern __shared__ __align__(128) char sm[];
    const int z = blockIdx.z;
    const bf16 *Ah, *Al, *Bh, *Bl;
    bf16 *Ch, *Cl;
    if (z == 0)      { Ah=g_aqh; Al=g_aql; Bh=g_wqh; Bl=g_wql; Ch=g_qh; Cl=g_ql; }
    else if (z == 1) { Ah=g_akh; Al=g_akl; Bh=g_wkh; Bl=g_wkl; Ch=g_kh; Cl=g_kl; }
    else             { Ah=g_avh; Al=g_avl; Bh=g_wvh; Bl=g_wvl; Ch=g_vh; Cl=g_vl; }
    gemm_body(Ah, Al, Bh, Bl, nullptr, Ch, Cl, DD, DD, sm);
}

// output projection (fp32 out)
__global__ __launch_bounds__(256, 2)
void gemm_fc(float* __restrict__ Cf)
{
    extern __shared__ __align__(128) char sm[];
    gemm_body(g_ch, g_cl, g_wfh, g_wfl, Cf, nullptr, nullptr, DD, DD, sm);
}

// ============================================================
// fused flash attention: j-tile 64, 2 CTAs/SM, pre-split bf16 io
// (cs stores on P writes)
// ============================================================
#define KST 144
#define FBUF 36864
#define FKH(b) ((b)*FBUF)
#define FKL(b) ((b)*FBUF + 9216)
#define FVH(b) ((b)*FBUF + 18432)
#define FVL(b) ((b)*FBUF + 27648)
#define DYNSM_F 73728

__device__ __forceinline__ void stage_kv64_b(char* sm, int hOff, int lOff,
                                             const bf16* srcH, const bf16* srcL, int t)
{
    const int row = t >> 2, ch = t & 3;
    const size_t g = (size_t)row*DD + ch*16;
    const int so = row*KST + ch*32;
    *(uint4*)(sm + hOff + so)      = *(const uint4*)(srcH + g);
    *(uint4*)(sm + hOff + so + 16) = *(const uint4*)(srcH + g + 8);
    *(uint4*)(sm + lOff + so)      = *(const uint4*)(srcL + g);
    *(uint4*)(sm + lOff + so + 16) = *(const uint4*)(srcL + g + 8);
}
__device__ __forceinline__ void stage_q128_b(char* sm, int hOff, int lOff,
                                             const bf16* srcH, const bf16* srcL, int t)
{
    const int row = t >> 1, half = t & 1;
    const size_t g = (size_t)row*DD + half*32;
    const int so = row*KST + half*64;
#pragma unroll
    for (int q = 0; q < 4; q++) {
        *(uint4*)(sm + hOff + so + q*16) = *(const uint4*)(srcH + g + q*8);
        *(uint4*)(sm + lOff + so + q*16) = *(const uint4*)(srcL + g + q*8);
    }
}

__global__ __launch_bounds__(256, 2)
void flash_attn(const int* __restrict__ mask, float* __restrict__ attn)
{
    extern __shared__ __align__(128) char sm[];
    const uint32_t smb = smem_u32(sm);
    const int t = threadIdx.x;
    const int lane = t & 31, w = t >> 5;
    const int rbk = blockIdx.x, bh = blockIdx.y;
    const int b = bh >> 4, h = bh & 15;
    const int i0 = rbk * 128;

    const size_t qoff = ((size_t)b*SS + i0)*DD + h*DK;
    const size_t koff = (size_t)b*SS*DD + h*DK;

    stage_q128_b(sm, 0, 18432, g_qh + qoff, g_ql + qoff, t);
    __syncthreads();

    uint32_t Qh[4][4], Ql[4][4];
    {
        const uint32_t a_base = (uint32_t)((w*16 + (lane & 15))*KST + ((lane >> 4) & 1)*16);
#pragma unroll
        for (int c = 0; c < 4; c++) {
            ldsm_x4(Qh[c], smb + a_base + c*32);
            ldsm_x4(Ql[c], smb + 18432 + a_base + c*32);
        }
    }
    __syncthreads();

    stage_kv64_b(sm, FKH(0), FKL(0), g_kh + koff, g_kl + koff, t);
    stage_kv64_b(sm, FVH(0), FVL(0), g_vh + koff, g_vl + koff, t);
    __syncthreads();

    float accO[8][4];
#pragma unroll
    for (int a = 0; a < 8; a++)
#pragma unroll
        for (int c = 0; c < 4; c++) accO[a][c] = 0.f;
    float lrun[2] = {0.f, 0.f};

    const int* mb = mask + (size_t)b*SS*SS;
    float* arow = attn + (size_t)bh*SS*SS;
    const int r0l = w*16 + (lane >> 2);
    const int qrow = lane & 3;
    const int gi0 = i0 + r0l;

    const uint32_t kb_base = (uint32_t)(((lane & 7) + ((lane >> 4) & 1)*8)*KST
                                        + ((lane >> 3) & 1)*16);
    const uint32_t vb_base = (uint32_t)(((lane & 7) + ((lane >> 3) & 1)*8)*KST
                                        + ((lane >> 4) & 1)*16);

    for (int jt = 0; jt < 32; jt++) {
        const int buf = jt & 1;
        if (jt + 1 < 32) {
            const size_t nk = koff + (size_t)(jt+1)*64*DD;
            stage_kv64_b(sm, FKH(buf^1), FKL(buf^1), g_kh + nk, g_kl + nk, t);
            stage_kv64_b(sm, FVH(buf^1), FVL(buf^1), g_vh + nk, g_vl + nk, t);
        }

        // ---- S = Q K^T (3-product split) ----
        float accS[8][4];
#pragma unroll
        for (int a = 0; a < 8; a++)
#pragma unroll
            for (int c = 0; c < 4; c++) accS[a][c] = 0.f;
#pragma unroll
        for (int c = 0; c < 4; c++) {
#pragma unroll
            for (int jg = 0; jg < 4; jg++) {
                uint32_t Kh4[4], Kl4[4];
                const uint32_t ko = kb_base + (uint32_t)(jg*16*KST + c*32);
                ldsm_x4(Kh4, smb + FKH(buf) + ko);
                ldsm_x4(Kl4, smb + FKL(buf) + ko);
                mma_bf16(accS[2*jg],   Qh[c], Kh4);
                mma_bf16(accS[2*jg+1], Qh[c], Kh4 + 2);
                mma_bf16(accS[2*jg],   Ql[c], Kh4);
                mma_bf16(accS[2*jg+1], Ql[c], Kh4 + 2);
                mma_bf16(accS[2*jg],   Qh[c], Kl4);
                mma_bf16(accS[2*jg+1], Qh[c], Kl4 + 2);
            }
        }

        // ---- mask + scale + exp + row-sum ----
        float es0 = 0.f, es1 = 0.f;
#pragma unroll
        for (int tj = 0; tj < 8; tj++) {
            const int j = jt*64 + tj*8 + qrow*2;
            int2 m0 = *(const int2*)&mb[(size_t)gi0*SS + j];
            int2 m1 = *(const int2*)&mb[(size_t)(gi0+8)*SS + j];
            float e0 = m0.x ? 0.f : __expf(accS[tj][0]*0.125f);
            float e1 = m0.y ? 0.f : __expf(accS[tj][1]*0.125f);
            float e2 = m1.x ? 0.f : __expf(accS[tj][2]*0.125f);
            float e3 = m1.y ? 0.f : __expf(accS[tj][3]*0.125f);
            accS[tj][0] = e0; accS[tj][1] = e1;
            accS[tj][2] = e2; accS[tj][3] = e3;
            es0 += e0 + e1;
            es1 += e2 + e3;
        }
        es0 += __shfl_xor_sync(0xffffffffu, es0, 1);
        es0 += __shfl_xor_sync(0xffffffffu, es0, 2);
        es1 += __shfl_xor_sync(0xffffffffu, es1, 1);
        es1 += __shfl_xor_sync(0xffffffffu, es1, 2);
        lrun[0] += es0;
        lrun[1] += es1;

        // ---- write unnormalized P (streaming stores) ----
#pragma unroll
        for (int tj = 0; tj < 8; tj++) {
            const int j = jt*64 + tj*8 + qrow*2;
            stg_cs_f2(&arow[(size_t)gi0*SS + j],     accS[tj][0], accS[tj][1]);
            stg_cs_f2(&arow[(size_t)(gi0+8)*SS + j], accS[tj][2], accS[tj][3]);
        }

        // ---- O += P @ V (3-product split) ----
#pragma unroll
        for (int q = 0; q < 4; q++) {
            uint32_t ah[4], al[4];
            ah[0] = packhl(accS[2*q][0],   accS[2*q][1],   al[0]);
            ah[1] = packhl(accS[2*q][2],   accS[2*q][3],   al[1]);
            ah[2] = packhl(accS[2*q+1][0], accS[2*q+1][1], al[2]);
            ah[3] = packhl(accS[2*q+1][2], accS[2*q+1][3], al[3]);
#pragma unroll
            for (int vg = 0; vg < 4; vg++) {
                uint32_t Vh4[4], Vl4[4];
                const uint32_t vo = vb_base + (uint32_t)(q*16*KST + vg*32);
                ldsm_x4_t(Vh4, smb + FVH(buf) + vo);
                ldsm_x4_t(Vl4, smb + FVL(buf) + vo);
                mma_bf16(accO[2*vg],   ah, Vh4);
                mma_bf16(accO[2*vg+1], ah, Vh4 + 2);
                mma_bf16(accO[2*vg],   al, Vh4);
                mma_bf16(accO[2*vg+1], al, Vh4 + 2);
                mma_bf16(accO[2*vg],   ah, Vl4);
                mma_bf16(accO[2*vg+1], ah, Vl4 + 2);
            }
        }
        __syncthreads();
    }

    // ---- finalize: row sums + ctx written as bf16 hi/lo ----
    if ((lane & 3) == 0) {
        g_ls[(size_t)bh*SS + gi0]     = lrun[0];
        g_ls[(size_t)bh*SS + gi0 + 8] = lrun[1];
    }
    const float rl0 = 1.f / lrun[0];
    const float rl1 = 1.f / lrun[1];
    const size_t c0 = ((size_t)b*SS + gi0)*DD + h*DK + qrow*2;
#pragma unroll
    for (int nj = 0; nj < 8; nj++) {
        uint32_t lo0, lo1;
        uint32_t hi0 = packhl(accO[nj][0]*rl0, accO[nj][1]*rl0, lo0);
        uint32_t hi1 = packhl(accO[nj][2]*rl1, accO[nj][3]*rl1, lo1);
        *(uint32_t*)&g_ch[c0 + nj*8]        = hi0;
        *(uint32_t*)&g_cl[c0 + nj*8]        = lo0;
        *(uint32_t*)&g_ch[c0 + 8*DD + nj*8] = hi1;
        *(uint32_t*)&g_cl[c0 + 8*DD + nj*8] = lo1;
    }
}

// ============================================================
// attn normalization: attn *= 1/l  (plain)
// ============================================================
__global__ void fix_attn(float* __restrict__ attn)
{
    const int blk = blockIdx.x;
    const int bh = blk >> 11, row = blk & 2047;
    const float linv = 1.0f / g_ls[(size_t)bh*SS + row];
    const int t = threadIdx.x;
    const size_t base = ((size_t)bh*SS + row)*SS;
    const int c0 = t*4, c1 = 1024 + t*4;
    float4 v0 = *(float4*)(attn + base + c0);
    float4 v1 = *(float4*)(attn + base + c1);
    v0.x *= linv; v0.y *= linv; v0.z *= linv; v0.w *= linv;
    v1.x *= linv; v1.y *= linv; v1.z *= linv; v1.w *= linv;
    *(float4*)(attn + base + c0) = v0;
    *(float4*)(attn + base + c1) = v1;
}

// ============================================================
// out = LayerNorm(pre + residual)
// ============================================================
__global__ void ln_kernel(const float* __restrict__ resid,
                          float* __restrict__ out)
{
    const size_t base = (size_t)blockIdx.x * DD;
    const int t = threadIdx.x;
    __shared__ float red1[8];
    __shared__ float red2[8];

    float v[4];
    float s = 0.f;
#pragma unroll
    for (int j = 0; j < 4; j++) {
        v[j] = g_pre[base + t + 256*j] + resid[base + t + 256*j];
        s += v[j];
    }
#pragma unroll
    for (int o = 16; o > 0; o >>= 1) s += __shfl_xor_sync(0xffffffffu, s, o);
    if ((t & 31) == 0) red1[t >> 5] = s;
    __syncthreads();
    s = red1[0];
#pragma unroll
    for (int w = 1; w < 8; w++) s += red1[w];
    const float mu = s * (1.0f / DD);

    float sq = 0.f;
#pragma unroll
    for (int j = 0; j < 4; j++) { const float d = v[j] - mu; sq += d*d; }
#pragma unroll
    for (int o = 16; o > 0; o >>= 1) sq += __shfl_xor_sync(0xffffffffu, sq, o);
    if ((t & 31) == 0) red2[t >> 5] = sq;
    __syncthreads();
    sq = red2[0];
#pragma unroll
    for (int w = 1; w < 8; w++) sq += red2[w];
    const float inv = rsqrtf(sq * (1.0f / DD) + 1e-5f);

#pragma unroll
    for (int j = 0; j < 4; j++) out[base + t + 256*j] = (v[j] - mu) * inv;
}

// ============================================================
extern "C" void kernel_launch(void* const* d_in, const int* in_sizes, int n_in,
                              void* d_out, int out_size)
{
    const float* inQ  = (const float*)d_in[0];
    const float* inK  = (const float*)d_in[1];
    const float* inV  = (const float*)d_in[2];
    const int*   mask = (const int*)  d_in[3];
    const float* WQ   = (const float*)d_in[4];
    const float* WK   = (const float*)d_in[5];
    const float* WV   = (const float*)d_in[6];
    const float* Wfc  = (const float*)d_in[7];
    float* out = (float*)d_out;

    bf16 *aqh, *aql, *akh, *akl, *avh, *avl;
    bf16 *wqh, *wql, *wkh, *wkl, *wvh, *wvl, *wfh, *wfl;
    float *ppre, *psc, *pdmy;
    cudaGetSymbolAddress((void**)&aqh, g_aqh); cudaGetSymbolAddress((void**)&aql, g_aql);
    cudaGetSymbolAddress((void**)&akh, g_akh); cudaGetSymbolAddress((void**)&akl, g_akl);
    cudaGetSymbolAddress((void**)&avh, g_avh); cudaGetSymbolAddress((void**)&avl, g_avl);
    cudaGetSymbolAddress((void**)&wqh, g_wqh); cudaGetSymbolAddress((void**)&wql, g_wql);
    cudaGetSymbolAddress((void**)&wkh, g_wkh); cudaGetSymbolAddress((void**)&wkl, g_wkl);
    cudaGetSymbolAddress((void**)&wvh, g_wvh); cudaGetSymbolAddress((void**)&wvl, g_wvl);
    cudaGetSymbolAddress((void**)&wfh, g_wfh); cudaGetSymbolAddress((void**)&wfl, g_wfl);
    cudaGetSymbolAddress((void**)&ppre, g_pre);
    cudaGetSymbolAddress((void**)&psc,  g_scores);
    cudaGetSymbolAddress((void**)&pdmy, g_dummy_out);

    const long long OUT_E  = (long long)NT * DD;
    const long long ATTN_E = (long long)BB * HH * SS * SS;

    float* out_dst  = out;
    float* attn_dst = psc;
    if ((long long)out_size >= OUT_E + ATTN_E) {
        attn_dst = out + OUT_E;
    } else if ((long long)out_size == ATTN_E) {
        attn_dst = out;
        out_dst  = pdmy;
    }

    cudaFuncSetAttribute(flash_attn, cudaFuncAttributeMaxDynamicSharedMemorySize, DYNSM_F);

    const dim3 blk(256);
    const int NACT = NT*DD/1024;
    const int NW   = DD*DD/1024;

    // pre-split inputs + weights
    presplit<<<NACT, blk>>>((const float4*)inQ, (uint2*)aqh, (uint2*)aql);
    presplit<<<NACT, blk>>>((const float4*)inK, (uint2*)akh, (uint2*)akl);
    presplit<<<NACT, blk>>>((const float4*)inV, (uint2*)avh, (uint2*)avl);
    presplit<<<NW,   blk>>>((const float4*)WQ,  (uint2*)wqh, (uint2*)wql);
    presplit<<<NW,   blk>>>((const float4*)WK,  (uint2*)wkh, (uint2*)wkl);
    presplit<<<NW,   blk>>>((const float4*)WV,  (uint2*)wvh, (uint2*)wvl);
    presplit<<<NW,   blk>>>((const float4*)Wfc, (uint2*)wfh, (uint2*)wfl);

    // QKV projections fused into one launch (z selects operand set)
    gemm_qkv<<<dim3(DD/128, NT/128, 3), blk, DYNSM>>>();

    // fused attention
    flash_attn<<<dim3(16, BB*HH), blk, DYNSM_F>>>(mask, attn_dst);

    // normalize attn in-place
    fix_attn<<<(unsigned)(BB*HH*SS), blk>>>(attn_dst);

    // output projection (fp32 out for LN)
    gemm_fc<<<dim3(DD/128, NT/128), blk, DYNSM>>>(ppre);

    // residual + layernorm
    ln_kernel<<<(unsigned)NT, blk>>>(inQ, out_dst);
}

// round 14
// speedup vs baseline: 1.0657x; 1.0657x over previous
#include <cuda_runtime.h>
#include <cuda_bf16.h>
#include <cuda_fp16.h>
#include <cstdint>
#include <math.h>

#define BB 2
#define SS 2048
#define DD 1024
#define HH 16
#define DK 64
#define NT (BB*SS)   // 4096 tokens

typedef __nv_bfloat16 bf16;

// ---- scratch (static device globals; no allocations) ----
__device__ bf16 g_aqh[(size_t)NT*DD], g_aql[(size_t)NT*DD];
__device__ bf16 g_akh[(size_t)NT*DD], g_akl[(size_t)NT*DD];
__device__ bf16 g_avh[(size_t)NT*DD], g_avl[(size_t)NT*DD];
__device__ bf16 g_wqh[(size_t)DD*DD], g_wql[(size_t)DD*DD];
__device__ bf16 g_wkh[(size_t)DD*DD], g_wkl[(size_t)DD*DD];
__device__ bf16 g_wvh[(size_t)DD*DD], g_wvl[(size_t)DD*DD];
__device__ bf16 g_wfh[(size_t)DD*DD], g_wfl[(size_t)DD*DD];
__device__ bf16 g_qh[(size_t)NT*DD], g_ql[(size_t)NT*DD];
__device__ bf16 g_kh[(size_t)NT*DD], g_kl[(size_t)NT*DD];
__device__ bf16 g_vh[(size_t)NT*DD], g_vl[(size_t)NT*DD];
__device__ bf16 g_ch[(size_t)NT*DD], g_cl[(size_t)NT*DD];
__device__ float g_pre[(size_t)NT*DD];
__device__ __half g_ph[(size_t)BB*HH*SS*SS];      // unnormalized P (fp16 scratch)
__device__ float g_scores[(size_t)BB*HH*SS*SS];   // fallback attn target only
__device__ float g_dummy_out[(size_t)NT*DD];
__device__ float g_ls[(size_t)32*SS];             // row sums

// ============================================================
// warp-MMA helpers (baseline PTX: sm_80+, no 'a' features)
// ============================================================
__device__ __forceinline__ uint32_t smem_u32(const void* p) {
    uint32_t a;
    asm("{ .reg .u64 t; cvta.to.shared.u64 t, %1; cvt.u32.u64 %0, t; }"
        : "=r"(a) : "l"(p));
    return a;
}
__device__ __forceinline__ void ldsm_x4(uint32_t* r, uint32_t addr) {
    asm volatile("ldmatrix.sync.aligned.m8n8.x4.shared.b16 {%0,%1,%2,%3}, [%4];"
        : "=r"(r[0]), "=r"(r[1]), "=r"(r[2]), "=r"(r[3]) : "r"(addr));
}
__device__ __forceinline__ void ldsm_x4_t(uint32_t* r, uint32_t addr) {
    asm volatile("ldmatrix.sync.aligned.m8n8.x4.trans.shared.b16 {%0,%1,%2,%3}, [%4];"
        : "=r"(r[0]), "=r"(r[1]), "=r"(r[2]), "=r"(r[3]) : "r"(addr));
}
__device__ __forceinline__ void mma_bf16(float* c, const uint32_t* a, const uint32_t* b) {
    asm volatile(
        "mma.sync.aligned.m16n8k16.row.col.f32.bf16.bf16.f32 "
        "{%0,%1,%2,%3}, {%4,%5,%6,%7}, {%8,%9}, {%0,%1,%2,%3};"
        : "+f"(c[0]), "+f"(c[1]), "+f"(c[2]), "+f"(c[3])
        : "r"(a[0]), "r"(a[1]), "r"(a[2]), "r"(a[3]), "r"(b[0]), "r"(b[1]));
}
__device__ __forceinline__ uint32_t packhl(float a, float b, uint32_t& lo) {
    __nv_bfloat162 hb = __float22bfloat162_rn(make_float2(a, b));
    float2 hf = __bfloat1622float2(hb);
    __nv_bfloat162 lb = __float22bfloat162_rn(make_float2(a - hf.x, b - hf.y));
    lo = *(uint32_t*)&lb;
    return *(uint32_t*)&hb;
}
__device__ __forceinline__ void stg_cs_u32(__half* p, uint32_t v) {
    asm volatile("st.global.cs.b32 [%0], %1;" :: "l"(p), "r"(v));
}

// ============================================================
// pre-split: fp32 tensor -> bf16 hi/lo
// ============================================================
__global__ void presplit(const float4* __restrict__ x,
                         uint2* __restrict__ hi, uint2* __restrict__ lo)
{
    const int i = blockIdx.x*blockDim.x + threadIdx.x;
    float4 v = x[i];
    __nv_bfloat162 h01 = __float22bfloat162_rn(make_float2(v.x, v.y));
    __nv_bfloat162 h23 = __float22bfloat162_rn(make_float2(v.z, v.w));
    float2 f01 = __bfloat1622float2(h01);
    float2 f23 = __bfloat1622float2(h23);
    __nv_bfloat162 l01 = __float22bfloat162_rn(make_float2(v.x - f01.x, v.y - f01.y));
    __nv_bfloat162 l23 = __float22bfloat162_rn(make_float2(v.z - f23.x, v.w - f23.y));
    hi[i] = make_uint2(*(uint32_t*)&h01, *(uint32_t*)&h23);
    lo[i] = make_uint2(*(uint32_t*)&l01, *(uint32_t*)&l23);
}

// smem tile layout for gemm (per buffer): Ah,Al,Bh,Bl each 128 rows x 48 bytes
#define T_AH 0
#define T_AL 6144
#define T_BH 12288
#define T_BL 18432
#define BUFB 24576
#define DYNSM (2*BUFB)   // 48KB

__device__ __forceinline__ void mma_pass(float acc[2][8][4],
                                         uint32_t Af[2][4], uint32_t Bf[4][4])
{
#pragma unroll
    for (int ti = 0; ti < 2; ti++)
#pragma unroll
        for (int tj = 0; tj < 8; tj++)
            mma_bf16(acc[ti][tj], Af[ti], &Bf[tj >> 1][(tj & 1) * 2]);
}

// ============================================================
// gemm on pre-split bf16: C[M,N] = A[M,K] @ B[N,K]^T
// ============================================================
__global__ __launch_bounds__(256, 2)
void gemm_mma_b(const bf16* __restrict__ Ah, const bf16* __restrict__ Al,
                const bf16* __restrict__ Bh, const bf16* __restrict__ Bl,
                float* __restrict__ Cf, bf16* __restrict__ Ch, bf16* __restrict__ Cl,
                int N, int K)
{
    extern __shared__ __align__(128) char sm[];
    const uint32_t smb = smem_u32(sm);
    const int t = threadIdx.x;
    const int lane = t & 31, warp = t >> 5;
    const int wm = warp >> 1, wn = warp & 1;
    const int i0 = blockIdx.y * 128, j0 = blockIdx.x * 128;

    float acc[2][8][4];
#pragma unroll
    for (int a = 0; a < 2; a++)
#pragma unroll
        for (int b = 0; b < 8; b++)
#pragma unroll
            for (int c = 0; c < 4; c++) acc[a][b][c] = 0.f;

    const int r = t >> 1, kc = (t & 1) * 8;
    const int stoff = r * 48 + (t & 1) * 16;
    const bf16* pAh = Ah + (size_t)(i0 + r) * K + kc;
    const bf16* pAl = Al + (size_t)(i0 + r) * K + kc;
    const bf16* pBh = Bh + (size_t)(j0 + r) * K + kc;
    const bf16* pBl = Bl + (size_t)(j0 + r) * K + kc;

    const uint32_t a_off = (uint32_t)((wm*32 + (lane & 15)) * 48 + ((lane >> 4) & 1) * 16);
    const uint32_t b_off = (uint32_t)((wn*64 + (lane & 7) + ((lane >> 4) & 1) * 8) * 48
                                      + ((lane >> 3) & 1) * 16);

    *(uint4*)(sm + T_AH + stoff) = *(const uint4*)pAh;
    *(uint4*)(sm + T_AL + stoff) = *(const uint4*)pAl;
    *(uint4*)(sm + T_BH + stoff) = *(const uint4*)pBh;
    *(uint4*)(sm + T_BL + stoff) = *(const uint4*)pBl;
    __syncthreads();

    const int nst = K / 16;
    for (int s = 0; s < nst; s++) {
        const int buf = (s & 1) * BUFB;
        const bool more = (s + 1 < nst);
        uint4 nA, nAl, nB, nBl;
        if (more) {
            nA  = *(const uint4*)(pAh + (s+1)*16);
            nAl = *(const uint4*)(pAl + (s+1)*16);
            nB  = *(const uint4*)(pBh + (s+1)*16);
            nBl = *(const uint4*)(pBl + (s+1)*16);
        }
        uint32_t Af[2][4], Bf[4][4], X[4][4];
#pragma unroll
        for (int ti = 0; ti < 2; ti++)
            ldsm_x4(Af[ti], smb + buf + T_AH + a_off + ti*16*48);
#pragma unroll
        for (int pj = 0; pj < 4; pj++)
            ldsm_x4(Bf[pj], smb + buf + T_BH + b_off + pj*16*48);
        mma_pass(acc, Af, Bf);
#pragma unroll
        for (int pj = 0; pj < 4; pj++)
            ldsm_x4(X[pj], smb + buf + T_BL + b_off + pj*16*48);
        mma_pass(acc, Af, X);
#pragma unroll
        for (int ti = 0; ti < 2; ti++)
            ldsm_x4(X[ti], smb + buf + T_AL + a_off + ti*16*48);
        mma_pass(acc, X, Bf);

        if (more) {
            __syncthreads();
            const int nb = buf ^ BUFB;
            *(uint4*)(sm + nb + T_AH + stoff) = nA;
            *(uint4*)(sm + nb + T_AL + stoff) = nAl;
            *(uint4*)(sm + nb + T_BH + stoff) = nB;
            *(uint4*)(sm + nb + T_BL + stoff) = nBl;
            __syncthreads();
        }
    }

    const int rb = i0 + wm*32 + (lane >> 2);
    const int cb = j0 + wn*64 + (lane & 3) * 2;
    if (Cf) {
#pragma unroll
        for (int ti = 0; ti < 2; ti++)
#pragma unroll
            for (int tj = 0; tj < 8; tj++) {
                const int i = rb + ti*16, j = cb + tj*8;
                *(float2*)&Cf[(size_t)i*N + j]     = make_float2(acc[ti][tj][0], acc[ti][tj][1]);
                *(float2*)&Cf[(size_t)(i+8)*N + j] = make_float2(acc[ti][tj][2], acc[ti][tj][3]);
            }
    } else {
#pragma unroll
        for (int ti = 0; ti < 2; ti++)
#pragma unroll
            for (int tj = 0; tj < 8; tj++) {
                const int i = rb + ti*16, j = cb + tj*8;
                uint32_t lo0, lo1;
                uint32_t hi0 = packhl(acc[ti][tj][0], acc[ti][tj][1], lo0);
                uint32_t hi1 = packhl(acc[ti][tj][2], acc[ti][tj][3], lo1);
                *(uint32_t*)&Ch[(size_t)i*N + j]     = hi0;
                *(uint32_t*)&Cl[(size_t)i*N + j]     = lo0;
                *(uint32_t*)&Ch[(size_t)(i+8)*N + j] = hi1;
                *(uint32_t*)&Cl[(size_t)(i+8)*N + j] = lo1;
            }
    }
}

// ============================================================
// fused flash attention: j-tile 64, 2 CTAs/SM, pre-split bf16 io
// P stored as fp16 (cs) to g_ph scratch.
// ============================================================
#define KST 144
#define FBUF 36864
#define FKH(b) ((b)*FBUF)
#define FKL(b) ((b)*FBUF + 9216)
#define FVH(b) ((b)*FBUF + 18432)
#define FVL(b) ((b)*FBUF + 27648)
#define DYNSM_F 73728

__device__ __forceinline__ void stage_kv64_b(char* sm, int hOff, int lOff,
                                             const bf16* srcH, const bf16* srcL, int t)
{
    const int row = t >> 2, ch = t & 3;
    const size_t g = (size_t)row*DD + ch*16;
    const int so = row*KST + ch*32;
    *(uint4*)(sm + hOff + so)      = *(const uint4*)(srcH + g);
    *(uint4*)(sm + hOff + so + 16) = *(const uint4*)(srcH + g + 8);
    *(uint4*)(sm + lOff + so)      = *(const uint4*)(srcL + g);
    *(uint4*)(sm + lOff + so + 16) = *(const uint4*)(srcL + g + 8);
}
__device__ __forceinline__ void stage_q128_b(char* sm, int hOff, int lOff,
                                             const bf16* srcH, const bf16* srcL, int t)
{
    const int row = t >> 1, half = t & 1;
    const size_t g = (size_t)row*DD + half*32;
    const int so = row*KST + half*64;
#pragma unroll
    for (int q = 0; q < 4; q++) {
        *(uint4*)(sm + hOff + so + q*16) = *(const uint4*)(srcH + g + q*8);
        *(uint4*)(sm + lOff + so + q*16) = *(const uint4*)(srcL + g + q*8);
    }
}

__global__ __launch_bounds__(256, 2)
void flash_attn(const int* __restrict__ mask)
{
    extern __shared__ __align__(128) char sm[];
    const uint32_t smb = smem_u32(sm);
    const int t = threadIdx.x;
    const int lane = t & 31, w = t >> 5;
    const int rbk = blockIdx.x, bh = blockIdx.y;
    const int b = bh >> 4, h = bh & 15;
    const int i0 = rbk * 128;

    const size_t qoff = ((size_t)b*SS + i0)*DD + h*DK;
    const size_t koff = (size_t)b*SS*DD + h*DK;

    stage_q128_b(sm, 0, 18432, g_qh + qoff, g_ql + qoff, t);
    __syncthreads();

    uint32_t Qh[4][4], Ql[4][4];
    {
        const uint32_t a_base = (uint32_t)((w*16 + (lane & 15))*KST + ((lane >> 4) & 1)*16);
#pragma unroll
        for (int c = 0; c < 4; c++) {
            ldsm_x4(Qh[c], smb + a_base + c*32);
            ldsm_x4(Ql[c], smb + 18432 + a_base + c*32);
        }
    }
    __syncthreads();

    stage_kv64_b(sm, FKH(0), FKL(0), g_kh + koff, g_kl + koff, t);
    stage_kv64_b(sm, FVH(0), FVL(0), g_vh + koff, g_vl + koff, t);
    __syncthreads();

    float accO[8][4];
#pragma unroll
    for (int a = 0; a < 8; a++)
#pragma unroll
        for (int c = 0; c < 4; c++) accO[a][c] = 0.f;
    float lrun[2] = {0.f, 0.f};

    const int* mb = mask + (size_t)b*SS*SS;
    __half* prow = g_ph + (size_t)bh*SS*SS;
    const int r0l = w*16 + (lane >> 2);
    const int qrow = lane & 3;
    const int gi0 = i0 + r0l;

    const uint32_t kb_base = (uint32_t)(((lane & 7) + ((lane >> 4) & 1)*8)*KST
                                        + ((lane >> 3) & 1)*16);
    const uint32_t vb_base = (uint32_t)(((lane & 7) + ((lane >> 3) & 1)*8)*KST
                                        + ((lane >> 4) & 1)*16);

    for (int jt = 0; jt < 32; jt++) {
        const int buf = jt & 1;
        if (jt + 1 < 32) {
            const size_t nk = koff + (size_t)(jt+1)*64*DD;
            stage_kv64_b(sm, FKH(buf^1), FKL(buf^1), g_kh + nk, g_kl + nk, t);
            stage_kv64_b(sm, FVH(buf^1), FVL(buf^1), g_vh + nk, g_vl + nk, t);
        }

        // ---- S = Q K^T (3-product split) ----
        float accS[8][4];
#pragma unroll
        for (int a = 0; a < 8; a++)
#pragma unroll
            for (int c = 0; c < 4; c++) accS[a][c] = 0.f;
#pragma unroll
        for (int c = 0; c < 4; c++) {
#pragma unroll
            for (int jg = 0; jg < 4; jg++) {
                uint32_t Kh4[4], Kl4[4];
                const uint32_t ko = kb_base + (uint32_t)(jg*16*KST + c*32);
                ldsm_x4(Kh4, smb + FKH(buf) + ko);
                ldsm_x4(Kl4, smb + FKL(buf) + ko);
                mma_bf16(accS[2*jg],   Qh[c], Kh4);
                mma_bf16(accS[2*jg+1], Qh[c], Kh4 + 2);
                mma_bf16(accS[2*jg],   Ql[c], Kh4);
                mma_bf16(accS[2*jg+1], Ql[c], Kh4 + 2);
                mma_bf16(accS[2*jg],   Qh[c], Kl4);
                mma_bf16(accS[2*jg+1], Qh[c], Kl4 + 2);
            }
        }

        // ---- mask + scale + exp + row-sum ----
        float es0 = 0.f, es1 = 0.f;
#pragma unroll
        for (int tj = 0; tj < 8; tj++) {
            const int j = jt*64 + tj*8 + qrow*2;
            int2 m0 = *(const int2*)&mb[(size_t)gi0*SS + j];
            int2 m1 = *(const int2*)&mb[(size_t)(gi0+8)*SS + j];
            float e0 = m0.x ? 0.f : __expf(accS[tj][0]*0.125f);
            float e1 = m0.y ? 0.f : __expf(accS[tj][1]*0.125f);
            float e2 = m1.x ? 0.f : __expf(accS[tj][2]*0.125f);
            float e3 = m1.y ? 0.f : __expf(accS[tj][3]*0.125f);
            accS[tj][0] = e0; accS[tj][1] = e1;
            accS[tj][2] = e2; accS[tj][3] = e3;
            es0 += e0 + e1;
            es1 += e2 + e3;
        }
        es0 += __shfl_xor_sync(0xffffffffu, es0, 1);
        es0 += __shfl_xor_sync(0xffffffffu, es0, 2);
        es1 += __shfl_xor_sync(0xffffffffu, es1, 1);
        es1 += __shfl_xor_sync(0xffffffffu, es1, 2);
        lrun[0] += es0;
        lrun[1] += es1;

        // ---- write unnormalized P as fp16 (streaming stores) ----
#pragma unroll
        for (int tj = 0; tj < 8; tj++) {
            const int j = jt*64 + tj*8 + qrow*2;
            __half2 p0 = __floats2half2_rn(accS[tj][0], accS[tj][1]);
            __half2 p1 = __floats2half2_rn(accS[tj][2], accS[tj][3]);
            stg_cs_u32(&prow[(size_t)gi0*SS + j],     *(uint32_t*)&p0);
            stg_cs_u32(&prow[(size_t)(gi0+8)*SS + j], *(uint32_t*)&p1);
        }

        // ---- O += P @ V (3-product split) ----
#pragma unroll
        for (int q = 0; q < 4; q++) {
            uint32_t ah[4], al[4];
            ah[0] = packhl(accS[2*q][0],   accS[2*q][1],   al[0]);
            ah[1] = packhl(accS[2*q][2],   accS[2*q][3],   al[1]);
            ah[2] = packhl(accS[2*q+1][0], accS[2*q+1][1], al[2]);
            ah[3] = packhl(accS[2*q+1][2], accS[2*q+1][3], al[3]);
#pragma unroll
            for (int vg = 0; vg < 4; vg++) {
                uint32_t Vh4[4], Vl4[4];
                const uint32_t vo = vb_base + (uint32_t)(q*16*KST + vg*32);
                ldsm_x4_t(Vh4, smb + FVH(buf) + vo);
                ldsm_x4_t(Vl4, smb + FVL(buf) + vo);
                mma_bf16(accO[2*vg],   ah, Vh4);
                mma_bf16(accO[2*vg+1], ah, Vh4 + 2);
                mma_bf16(accO[2*vg],   al, Vh4);
                mma_bf16(accO[2*vg+1], al, Vh4 + 2);
                mma_bf16(accO[2*vg],   ah, Vl4);
                mma_bf16(accO[2*vg+1], ah, Vl4 + 2);
            }
        }
        __syncthreads();
    }

    // ---- finalize: row sums + ctx written as bf16 hi/lo ----
    if ((lane & 3) == 0) {
        g_ls[(size_t)bh*SS + gi0]     = lrun[0];
        g_ls[(size_t)bh*SS + gi0 + 8] = lrun[1];
    }
    const float rl0 = 1.f / lrun[0];
    const float rl1 = 1.f / lrun[1];
    const size_t c0 = ((size_t)b*SS + gi0)*DD + h*DK + qrow*2;
#pragma unroll
    for (int nj = 0; nj < 8; nj++) {
        uint32_t lo0, lo1;
        uint32_t hi0 = packhl(accO[nj][0]*rl0, accO[nj][1]*rl0, lo0);
        uint32_t hi1 = packhl(accO[nj][2]*rl1, accO[nj][3]*rl1, lo1);
        *(uint32_t*)&g_ch[c0 + nj*8]        = hi0;
        *(uint32_t*)&g_cl[c0 + nj*8]        = lo0;
        *(uint32_t*)&g_ch[c0 + 8*DD + nj*8] = hi1;
        *(uint32_t*)&g_cl[c0 + 8*DD + nj*8] = lo1;
    }
}

// ============================================================
// attn normalization: attn = half(P) * (1/l)  -> fp32 out
// ============================================================
__global__ void fix_attn(float* __restrict__ attn)
{
    const int blk = blockIdx.x;
    const int bh = blk >> 11, row = blk & 2047;
    const float linv = 1.0f / g_ls[(size_t)bh*SS + row];
    const int t = threadIdx.x;
    const size_t base = ((size_t)bh*SS + row)*SS;
    // 2048 cols / 256 threads = 8 halves per thread = one uint4
    uint4 raw = *(const uint4*)(g_ph + base + t*8);
    const __half2* hp = (const __half2*)&raw;
    float* dst = attn + base + t*8;
    float2 f0 = __half22float2(hp[0]);
    float2 f1 = __half22float2(hp[1]);
    float2 f2 = __half22float2(hp[2]);
    float2 f3 = __half22float2(hp[3]);
    float4 o0 = make_float4(f0.x*linv, f0.y*linv, f1.x*linv, f1.y*linv);
    float4 o1 = make_float4(f2.x*linv, f2.y*linv, f3.x*linv, f3.y*linv);
    *(float4*)(dst)     = o0;
    *(float4*)(dst + 4) = o1;
}

// ============================================================
// out = LayerNorm(pre + residual)
// ============================================================
__global__ void ln_kernel(const float* __restrict__ resid,
                          float* __restrict__ out)
{
    const size_t base = (size_t)blockIdx.x * DD;
    const int t = threadIdx.x;
    __shared__ float red1[8];
    __shared__ float red2[8];

    float v[4];
    float s = 0.f;
#pragma unroll
    for (int j = 0; j < 4; j++) {
        v[j] = g_pre[base + t + 256*j] + resid[base + t + 256*j];
        s += v[j];
    }
#pragma unroll
    for (int o = 16; o > 0; o >>= 1) s += __shfl_xor_sync(0xffffffffu, s, o);
    if ((t & 31) == 0) red1[t >> 5] = s;
    __syncthreads();
    s = red1[0];
#pragma unroll
    for (int w = 1; w < 8; w++) s += red1[w];
    const float mu = s * (1.0f / DD);

    float sq = 0.f;
#pragma unroll
    for (int j = 0; j < 4; j++) { const float d = v[j] - mu; sq += d*d; }
#pragma unroll
    for (int o = 16; o > 0; o >>= 1) sq += __shfl_xor_sync(0xffffffffu, sq, o);
    if ((t & 31) == 0) red2[t >> 5] = sq;
    __syncthreads();
    sq = red2[0];
#pragma unroll
    for (int w = 1; w < 8; w++) sq += red2[w];
    const float inv = rsqrtf(sq * (1.0f / DD) + 1e-5f);

#pragma unroll
    for (int j = 0; j < 4; j++) out[base + t + 256*j] = (v[j] - mu) * inv;
}

// ============================================================
extern "C" void kernel_launch(void* const* d_in, const int* in_sizes, int n_in,
                              void* d_out, int out_size)
{
    const float* inQ  = (const float*)d_in[0];
    const float* inK  = (const float*)d_in[1];
    const float* inV  = (const float*)d_in[2];
    const int*   mask = (const int*)  d_in[3];
    const float* WQ   = (const float*)d_in[4];
    const float* WK   = (const float*)d_in[5];
    const float* WV   = (const float*)d_in[6];
    const float* Wfc  = (const float*)d_in[7];
    float* out = (float*)d_out;

    bf16 *aqh, *aql, *akh, *akl, *avh, *avl;
    bf16 *wqh, *wql, *wkh, *wkl, *wvh, *wvl, *wfh, *wfl;
    bf16 *qh, *ql, *kh, *kl, *vh, *vl, *ch, *cl;
    float *ppre, *psc, *pdmy;
    cudaGetSymbolAddress((void**)&aqh, g_aqh); cudaGetSymbolAddress((void**)&aql, g_aql);
    cudaGetSymbolAddress((void**)&akh, g_akh); cudaGetSymbolAddress((void**)&akl, g_akl);
    cudaGetSymbolAddress((void**)&avh, g_avh); cudaGetSymbolAddress((void**)&avl, g_avl);
    cudaGetSymbolAddress((void**)&wqh, g_wqh); cudaGetSymbolAddress((void**)&wql, g_wql);
    cudaGetSymbolAddress((void**)&wkh, g_wkh); cudaGetSymbolAddress((void**)&wkl, g_wkl);
    cudaGetSymbolAddress((void**)&wvh, g_wvh); cudaGetSymbolAddress((void**)&wvl, g_wvl);
    cudaGetSymbolAddress((void**)&wfh, g_wfh); cudaGetSymbolAddress((void**)&wfl, g_wfl);
    cudaGetSymbolAddress((void**)&qh, g_qh);   cudaGetSymbolAddress((void**)&ql, g_ql);
    cudaGetSymbolAddress((void**)&kh, g_kh);   cudaGetSymbolAddress((void**)&kl, g_kl);
    cudaGetSymbolAddress((void**)&vh, g_vh);   cudaGetSymbolAddress((void**)&vl, g_vl);
    cudaGetSymbolAddress((void**)&ch, g_ch);   cudaGetSymbolAddress((void**)&cl, g_cl);
    cudaGetSymbolAddress((void**)&ppre, g_pre);
    cudaGetSymbolAddress((void**)&psc,  g_scores);
    cudaGetSymbolAddress((void**)&pdmy, g_dummy_out);

    const long long OUT_E  = (long long)NT * DD;
    const long long ATTN_E = (long long)BB * HH * SS * SS;

    float* out_dst  = out;
    float* attn_dst = psc;
    if ((long long)out_size >= OUT_E + ATTN_E) {
        attn_dst = out + OUT_E;
    } else if ((long long)out_size == ATTN_E) {
        attn_dst = out;
        out_dst  = pdmy;
    }

    cudaFuncSetAttribute(flash_attn, cudaFuncAttributeMaxDynamicSharedMemorySize, DYNSM_F);

    const dim3 blk(256);
    const int NACT = NT*DD/1024;
    const int NW   = DD*DD/1024;

    // pre-split inputs + weights
    presplit<<<NACT, blk>>>((const float4*)inQ, (uint2*)aqh, (uint2*)aql);
    presplit<<<NACT, blk>>>((const float4*)inK, (uint2*)akh, (uint2*)akl);
    presplit<<<NACT, blk>>>((const float4*)inV, (uint2*)avh, (uint2*)avl);
    presplit<<<NW,   blk>>>((const float4*)WQ,  (uint2*)wqh, (uint2*)wql);
    presplit<<<NW,   blk>>>((const float4*)WK,  (uint2*)wkh, (uint2*)wkl);
    presplit<<<NW,   blk>>>((const float4*)WV,  (uint2*)wvh, (uint2*)wvl);
    presplit<<<NW,   blk>>>((const float4*)Wfc, (uint2*)wfh, (uint2*)wfl);

    // projections -> split bf16 outputs (separate launches: z-fusion blacklisted)
    gemm_mma_b<<<dim3(DD/128, NT/128), blk, DYNSM>>>(aqh, aql, wqh, wql, nullptr, qh, ql, DD, DD);
    gemm_mma_b<<<dim3(DD/128, NT/128), blk, DYNSM>>>(akh, akl, wkh, wkl, nullptr, kh, kl, DD, DD);
    gemm_mma_b<<<dim3(DD/128, NT/128), blk, DYNSM>>>(avh, avl, wvh, wvl, nullptr, vh, vl, DD, DD);

    // fused attention (P -> fp16 scratch)
    flash_attn<<<dim3(16, BB*HH), blk, DYNSM_F>>>(mask);

    // normalize: fp16 P -> fp32 attn
    fix_attn<<<(unsigned)(BB*HH*SS), blk>>>(attn_dst);

    // output projection (fp32 out for LN)
    gemm_mma_b<<<dim3(DD/128, NT/128), blk, DYNSM>>>(ch, cl, wfh, wfl, ppre, nullptr, nullptr, DD, DD);

    // residual + layernorm
    ln_kernel<<<(unsigned)NT, blk>>>(inQ, out_dst);
}

// round 15
// speedup vs baseline: 1.1371x; 1.0670x over previous
#include <cuda_runtime.h>
#include <cuda_bf16.h>
#include <cuda_fp16.h>
#include <cstdint>
#include <math.h>

#define BB 2
#define SS 2048
#define DD 1024
#define HH 16
#define DK 64
#define NT (BB*SS)   // 4096 tokens

typedef __nv_bfloat16 bf16;

// ---- scratch (static device globals; no allocations) ----
__device__ bf16 g_aqh[(size_t)NT*DD], g_aql[(size_t)NT*DD];
__device__ bf16 g_akh[(size_t)NT*DD], g_akl[(size_t)NT*DD];
__device__ bf16 g_avh[(size_t)NT*DD], g_avl[(size_t)NT*DD];
__device__ bf16 g_wqh[(size_t)DD*DD], g_wql[(size_t)DD*DD];
__device__ bf16 g_wkh[(size_t)DD*DD], g_wkl[(size_t)DD*DD];
__device__ bf16 g_wvh[(size_t)DD*DD], g_wvl[(size_t)DD*DD];
__device__ bf16 g_wfh[(size_t)DD*DD], g_wfl[(size_t)DD*DD];
__device__ bf16 g_qh[(size_t)NT*DD], g_ql[(size_t)NT*DD];
__device__ bf16 g_kh[(size_t)NT*DD], g_kl[(size_t)NT*DD];
__device__ bf16 g_vh[(size_t)NT*DD], g_vl[(size_t)NT*DD];
__device__ bf16 g_ch[(size_t)NT*DD], g_cl[(size_t)NT*DD];
__device__ float g_pre[(size_t)NT*DD];
__device__ __half g_ph[(size_t)BB*HH*SS*SS];      // unnormalized P (fp16 scratch)
__device__ float g_scores[(size_t)BB*HH*SS*SS];   // fallback attn target only
__device__ float g_dummy_out[(size_t)NT*DD];
__device__ float g_ls[(size_t)32*SS];             // row sums

// ============================================================
// warp-MMA helpers (baseline PTX: sm_80+, no 'a' features)
// ============================================================
__device__ __forceinline__ uint32_t smem_u32(const void* p) {
    uint32_t a;
    asm("{ .reg .u64 t; cvta.to.shared.u64 t, %1; cvt.u32.u64 %0, t; }"
        : "=r"(a) : "l"(p));
    return a;
}
__device__ __forceinline__ void ldsm_x4(uint32_t* r, uint32_t addr) {
    asm volatile("ldmatrix.sync.aligned.m8n8.x4.shared.b16 {%0,%1,%2,%3}, [%4];"
        : "=r"(r[0]), "=r"(r[1]), "=r"(r[2]), "=r"(r[3]) : "r"(addr));
}
__device__ __forceinline__ void ldsm_x4_t(uint32_t* r, uint32_t addr) {
    asm volatile("ldmatrix.sync.aligned.m8n8.x4.trans.shared.b16 {%0,%1,%2,%3}, [%4];"
        : "=r"(r[0]), "=r"(r[1]), "=r"(r[2]), "=r"(r[3]) : "r"(addr));
}
__device__ __forceinline__ void mma_bf16(float* c, const uint32_t* a, const uint32_t* b) {
    asm volatile(
        "mma.sync.aligned.m16n8k16.row.col.f32.bf16.bf16.f32 "
        "{%0,%1,%2,%3}, {%4,%5,%6,%7}, {%8,%9}, {%0,%1,%2,%3};"
        : "+f"(c[0]), "+f"(c[1]), "+f"(c[2]), "+f"(c[3])
        : "r"(a[0]), "r"(a[1]), "r"(a[2]), "r"(a[3]), "r"(b[0]), "r"(b[1]));
}
__device__ __forceinline__ uint32_t packhl(float a, float b, uint32_t& lo) {
    __nv_bfloat162 hb = __float22bfloat162_rn(make_float2(a, b));
    float2 hf = __bfloat1622float2(hb);
    __nv_bfloat162 lb = __float22bfloat162_rn(make_float2(a - hf.x, b - hf.y));
    lo = *(uint32_t*)&lb;
    return *(uint32_t*)&hb;
}
__device__ __forceinline__ void stg_cs_u32(__half* p, uint32_t v) {
    asm volatile("st.global.cs.b32 [%0], %1;" :: "l"(p), "r"(v));
}

// ============================================================
// pre-split: fp32 tensor -> bf16 hi/lo
// ============================================================
__global__ void presplit(const float4* __restrict__ x,
                         uint2* __restrict__ hi, uint2* __restrict__ lo)
{
    const int i = blockIdx.x*blockDim.x + threadIdx.x;
    float4 v = x[i];
    __nv_bfloat162 h01 = __float22bfloat162_rn(make_float2(v.x, v.y));
    __nv_bfloat162 h23 = __float22bfloat162_rn(make_float2(v.z, v.w));
    float2 f01 = __bfloat1622float2(h01);
    float2 f23 = __bfloat1622float2(h23);
    __nv_bfloat162 l01 = __float22bfloat162_rn(make_float2(v.x - f01.x, v.y - f01.y));
    __nv_bfloat162 l23 = __float22bfloat162_rn(make_float2(v.z - f23.x, v.w - f23.y));
    hi[i] = make_uint2(*(uint32_t*)&h01, *(uint32_t*)&h23);
    lo[i] = make_uint2(*(uint32_t*)&l01, *(uint32_t*)&l23);
}

// smem tile layout for gemm (per buffer): Ah,Al,Bh,Bl each 128 rows x 48 bytes
#define T_AH 0
#define T_AL 6144
#define T_BH 12288
#define T_BL 18432
#define BUFB 24576
#define DYNSM (2*BUFB)   // 48KB

__device__ __forceinline__ void mma_pass(float acc[2][8][4],
                                         uint32_t Af[2][4], uint32_t Bf[4][4])
{
#pragma unroll
    for (int ti = 0; ti < 2; ti++)
#pragma unroll
        for (int tj = 0; tj < 8; tj++)
            mma_bf16(acc[ti][tj], Af[ti], &Bf[tj >> 1][(tj & 1) * 2]);
}

// ============================================================
// gemm on pre-split bf16: C[M,N] = A[M,K] @ B[N,K]^T
// ============================================================
__global__ __launch_bounds__(256, 2)
void gemm_mma_b(const bf16* __restrict__ Ah, const bf16* __restrict__ Al,
                const bf16* __restrict__ Bh, const bf16* __restrict__ Bl,
                float* __restrict__ Cf, bf16* __restrict__ Ch, bf16* __restrict__ Cl,
                int N, int K)
{
    extern __shared__ __align__(128) char sm[];
    const uint32_t smb = smem_u32(sm);
    const int t = threadIdx.x;
    const int lane = t & 31, warp = t >> 5;
    const int wm = warp >> 1, wn = warp & 1;
    const int i0 = blockIdx.y * 128, j0 = blockIdx.x * 128;

    float acc[2][8][4];
#pragma unroll
    for (int a = 0; a < 2; a++)
#pragma unroll
        for (int b = 0; b < 8; b++)
#pragma unroll
            for (int c = 0; c < 4; c++) acc[a][b][c] = 0.f;

    const int r = t >> 1, kc = (t & 1) * 8;
    const int stoff = r * 48 + (t & 1) * 16;
    const bf16* pAh = Ah + (size_t)(i0 + r) * K + kc;
    const bf16* pAl = Al + (size_t)(i0 + r) * K + kc;
    const bf16* pBh = Bh + (size_t)(j0 + r) * K + kc;
    const bf16* pBl = Bl + (size_t)(j0 + r) * K + kc;

    const uint32_t a_off = (uint32_t)((wm*32 + (lane & 15)) * 48 + ((lane >> 4) & 1) * 16);
    const uint32_t b_off = (uint32_t)((wn*64 + (lane & 7) + ((lane >> 4) & 1) * 8) * 48
                                      + ((lane >> 3) & 1) * 16);

    *(uint4*)(sm + T_AH + stoff) = *(const uint4*)pAh;
    *(uint4*)(sm + T_AL + stoff) = *(const uint4*)pAl;
    *(uint4*)(sm + T_BH + stoff) = *(const uint4*)pBh;
    *(uint4*)(sm + T_BL + stoff) = *(const uint4*)pBl;
    __syncthreads();

    const int nst = K / 16;
    for (int s = 0; s < nst; s++) {
        const int buf = (s & 1) * BUFB;
        const bool more = (s + 1 < nst);
        uint4 nA, nAl, nB, nBl;
        if (more) {
            nA  = *(const uint4*)(pAh + (s+1)*16);
            nAl = *(const uint4*)(pAl + (s+1)*16);
            nB  = *(const uint4*)(pBh + (s+1)*16);
            nBl = *(const uint4*)(pBl + (s+1)*16);
        }
        uint32_t Af[2][4], Bf[4][4], X[4][4];
#pragma unroll
        for (int ti = 0; ti < 2; ti++)
            ldsm_x4(Af[ti], smb + buf + T_AH + a_off + ti*16*48);
#pragma unroll
        for (int pj = 0; pj < 4; pj++)
            ldsm_x4(Bf[pj], smb + buf + T_BH + b_off + pj*16*48);
        mma_pass(acc, Af, Bf);
#pragma unroll
        for (int pj = 0; pj < 4; pj++)
            ldsm_x4(X[pj], smb + buf + T_BL + b_off + pj*16*48);
        mma_pass(acc, Af, X);
#pragma unroll
        for (int ti = 0; ti < 2; ti++)
            ldsm_x4(X[ti], smb + buf + T_AL + a_off + ti*16*48);
        mma_pass(acc, X, Bf);

        if (more) {
            __syncthreads();
            const int nb = buf ^ BUFB;
            *(uint4*)(sm + nb + T_AH + stoff) = nA;
            *(uint4*)(sm + nb + T_AL + stoff) = nAl;
            *(uint4*)(sm + nb + T_BH + stoff) = nB;
            *(uint4*)(sm + nb + T_BL + stoff) = nBl;
            __syncthreads();
        }
    }

    const int rb = i0 + wm*32 + (lane >> 2);
    const int cb = j0 + wn*64 + (lane & 3) * 2;
    if (Cf) {
#pragma unroll
        for (int ti = 0; ti < 2; ti++)
#pragma unroll
            for (int tj = 0; tj < 8; tj++) {
                const int i = rb + ti*16, j = cb + tj*8;
                *(float2*)&Cf[(size_t)i*N + j]     = make_float2(acc[ti][tj][0], acc[ti][tj][1]);
                *(float2*)&Cf[(size_t)(i+8)*N + j] = make_float2(acc[ti][tj][2], acc[ti][tj][3]);
            }
    } else {
#pragma unroll
        for (int ti = 0; ti < 2; ti++)
#pragma unroll
            for (int tj = 0; tj < 8; tj++) {
                const int i = rb + ti*16, j = cb + tj*8;
                uint32_t lo0, lo1;
                uint32_t hi0 = packhl(acc[ti][tj][0], acc[ti][tj][1], lo0);
                uint32_t hi1 = packhl(acc[ti][tj][2], acc[ti][tj][3], lo1);
                *(uint32_t*)&Ch[(size_t)i*N + j]     = hi0;
                *(uint32_t*)&Cl[(size_t)i*N + j]     = lo0;
                *(uint32_t*)&Ch[(size_t)(i+8)*N + j] = hi1;
                *(uint32_t*)&Cl[(size_t)(i+8)*N + j] = lo1;
            }
    }
}

// ============================================================
// fused flash attention: j-tile 64, 2 CTAs/SM.
// V used as plain bf16 (hi only) in PV; P hi/lo kept.
// ============================================================
#define KST 144
#define FBUF 27648
#define FKH(b) ((b)*FBUF)
#define FKL(b) ((b)*FBUF + 9216)
#define FVH(b) ((b)*FBUF + 18432)
#define DYNSM_F 55296

__device__ __forceinline__ void stage_kv64_b(char* sm, int hOff, int lOff,
                                             const bf16* srcH, const bf16* srcL, int t)
{
    const int row = t >> 2, ch = t & 3;
    const size_t g = (size_t)row*DD + ch*16;
    const int so = row*KST + ch*32;
    *(uint4*)(sm + hOff + so)      = *(const uint4*)(srcH + g);
    *(uint4*)(sm + hOff + so + 16) = *(const uint4*)(srcH + g + 8);
    *(uint4*)(sm + lOff + so)      = *(const uint4*)(srcL + g);
    *(uint4*)(sm + lOff + so + 16) = *(const uint4*)(srcL + g + 8);
}
__device__ __forceinline__ void stage_v64(char* sm, int hOff,
                                          const bf16* srcH, int t)
{
    const int row = t >> 2, ch = t & 3;
    const size_t g = (size_t)row*DD + ch*16;
    const int so = row*KST + ch*32;
    *(uint4*)(sm + hOff + so)      = *(const uint4*)(srcH + g);
    *(uint4*)(sm + hOff + so + 16) = *(const uint4*)(srcH + g + 8);
}
__device__ __forceinline__ void stage_q128_b(char* sm, int hOff, int lOff,
                                             const bf16* srcH, const bf16* srcL, int t)
{
    const int row = t >> 1, half = t & 1;
    const size_t g = (size_t)row*DD + half*32;
    const int so = row*KST + half*64;
#pragma unroll
    for (int q = 0; q < 4; q++) {
        *(uint4*)(sm + hOff + so + q*16) = *(const uint4*)(srcH + g + q*8);
        *(uint4*)(sm + lOff + so + q*16) = *(const uint4*)(srcL + g + q*8);
    }
}

__global__ __launch_bounds__(256, 2)
void flash_attn(const int* __restrict__ mask)
{
    extern __shared__ __align__(128) char sm[];
    const uint32_t smb = smem_u32(sm);
    const int t = threadIdx.x;
    const int lane = t & 31, w = t >> 5;
    const int rbk = blockIdx.x, bh = blockIdx.y;
    const int b = bh >> 4, h = bh & 15;
    const int i0 = rbk * 128;

    const size_t qoff = ((size_t)b*SS + i0)*DD + h*DK;
    const size_t koff = (size_t)b*SS*DD + h*DK;

    stage_q128_b(sm, 0, 18432, g_qh + qoff, g_ql + qoff, t);
    __syncthreads();

    uint32_t Qh[4][4], Ql[4][4];
    {
        const uint32_t a_base = (uint32_t)((w*16 + (lane & 15))*KST + ((lane >> 4) & 1)*16);
#pragma unroll
        for (int c = 0; c < 4; c++) {
            ldsm_x4(Qh[c], smb + a_base + c*32);
            ldsm_x4(Ql[c], smb + 18432 + a_base + c*32);
        }
    }
    __syncthreads();

    stage_kv64_b(sm, FKH(0), FKL(0), g_kh + koff, g_kl + koff, t);
    stage_v64(sm, FVH(0), g_vh + koff, t);
    __syncthreads();

    float accO[8][4];
#pragma unroll
    for (int a = 0; a < 8; a++)
#pragma unroll
        for (int c = 0; c < 4; c++) accO[a][c] = 0.f;
    float lrun[2] = {0.f, 0.f};

    const int* mb = mask + (size_t)b*SS*SS;
    __half* prow = g_ph + (size_t)bh*SS*SS;
    const int r0l = w*16 + (lane >> 2);
    const int qrow = lane & 3;
    const int gi0 = i0 + r0l;

    const uint32_t kb_base = (uint32_t)(((lane & 7) + ((lane >> 4) & 1)*8)*KST
                                        + ((lane >> 3) & 1)*16);
    const uint32_t vb_base = (uint32_t)(((lane & 7) + ((lane >> 3) & 1)*8)*KST
                                        + ((lane >> 4) & 1)*16);

    for (int jt = 0; jt < 32; jt++) {
        const int buf = jt & 1;
        if (jt + 1 < 32) {
            const size_t nk = koff + (size_t)(jt+1)*64*DD;
            stage_kv64_b(sm, FKH(buf^1), FKL(buf^1), g_kh + nk, g_kl + nk, t);
            stage_v64(sm, FVH(buf^1), g_vh + nk, t);
        }

        // ---- S = Q K^T (3-product split) ----
        float accS[8][4];
#pragma unroll
        for (int a = 0; a < 8; a++)
#pragma unroll
            for (int c = 0; c < 4; c++) accS[a][c] = 0.f;
#pragma unroll
        for (int c = 0; c < 4; c++) {
#pragma unroll
            for (int jg = 0; jg < 4; jg++) {
                uint32_t Kh4[4], Kl4[4];
                const uint32_t ko = kb_base + (uint32_t)(jg*16*KST + c*32);
                ldsm_x4(Kh4, smb + FKH(buf) + ko);
                ldsm_x4(Kl4, smb + FKL(buf) + ko);
                mma_bf16(accS[2*jg],   Qh[c], Kh4);
                mma_bf16(accS[2*jg+1], Qh[c], Kh4 + 2);
                mma_bf16(accS[2*jg],   Ql[c], Kh4);
                mma_bf16(accS[2*jg+1], Ql[c], Kh4 + 2);
                mma_bf16(accS[2*jg],   Qh[c], Kl4);
                mma_bf16(accS[2*jg+1], Qh[c], Kl4 + 2);
            }
        }

        // ---- mask + scale + exp + row-sum ----
        float es0 = 0.f, es1 = 0.f;
#pragma unroll
        for (int tj = 0; tj < 8; tj++) {
            const int j = jt*64 + tj*8 + qrow*2;
            int2 m0 = *(const int2*)&mb[(size_t)gi0*SS + j];
            int2 m1 = *(const int2*)&mb[(size_t)(gi0+8)*SS + j];
            float e0 = m0.x ? 0.f : __expf(accS[tj][0]*0.125f);
            float e1 = m0.y ? 0.f : __expf(accS[tj][1]*0.125f);
            float e2 = m1.x ? 0.f : __expf(accS[tj][2]*0.125f);
            float e3 = m1.y ? 0.f : __expf(accS[tj][3]*0.125f);
            accS[tj][0] = e0; accS[tj][1] = e1;
            accS[tj][2] = e2; accS[tj][3] = e3;
            es0 += e0 + e1;
            es1 += e2 + e3;
        }
        es0 += __shfl_xor_sync(0xffffffffu, es0, 1);
        es0 += __shfl_xor_sync(0xffffffffu, es0, 2);
        es1 += __shfl_xor_sync(0xffffffffu, es1, 1);
        es1 += __shfl_xor_sync(0xffffffffu, es1, 2);
        lrun[0] += es0;
        lrun[1] += es1;

        // ---- write unnormalized P as fp16 (streaming stores) ----
#pragma unroll
        for (int tj = 0; tj < 8; tj++) {
            const int j = jt*64 + tj*8 + qrow*2;
            __half2 p0 = __floats2half2_rn(accS[tj][0], accS[tj][1]);
            __half2 p1 = __floats2half2_rn(accS[tj][2], accS[tj][3]);
            stg_cs_u32(&prow[(size_t)gi0*SS + j],     *(uint32_t*)&p0);
            stg_cs_u32(&prow[(size_t)(gi0+8)*SS + j], *(uint32_t*)&p1);
        }

        // ---- O += P @ V (P hi/lo x V bf16: 2 products) ----
#pragma unroll
        for (int q = 0; q < 4; q++) {
            uint32_t ah[4], al[4];
            ah[0] = packhl(accS[2*q][0],   accS[2*q][1],   al[0]);
            ah[1] = packhl(accS[2*q][2],   accS[2*q][3],   al[1]);
            ah[2] = packhl(accS[2*q+1][0], accS[2*q+1][1], al[2]);
            ah[3] = packhl(accS[2*q+1][2], accS[2*q+1][3], al[3]);
#pragma unroll
            for (int vg = 0; vg < 4; vg++) {
                uint32_t Vh4[4];
                const uint32_t vo = vb_base + (uint32_t)(q*16*KST + vg*32);
                ldsm_x4_t(Vh4, smb + FVH(buf) + vo);
                mma_bf16(accO[2*vg],   ah, Vh4);
                mma_bf16(accO[2*vg+1], ah, Vh4 + 2);
                mma_bf16(accO[2*vg],   al, Vh4);
                mma_bf16(accO[2*vg+1], al, Vh4 + 2);
            }
        }
        __syncthreads();
    }

    // ---- finalize: row sums + ctx written as bf16 hi/lo ----
    if ((lane & 3) == 0) {
        g_ls[(size_t)bh*SS + gi0]     = lrun[0];
        g_ls[(size_t)bh*SS + gi0 + 8] = lrun[1];
    }
    const float rl0 = 1.f / lrun[0];
    const float rl1 = 1.f / lrun[1];
    const size_t c0 = ((size_t)b*SS + gi0)*DD + h*DK + qrow*2;
#pragma unroll
    for (int nj = 0; nj < 8; nj++) {
        uint32_t lo0, lo1;
        uint32_t hi0 = packhl(accO[nj][0]*rl0, accO[nj][1]*rl0, lo0);
        uint32_t hi1 = packhl(accO[nj][2]*rl1, accO[nj][3]*rl1, lo1);
        *(uint32_t*)&g_ch[c0 + nj*8]        = hi0;
        *(uint32_t*)&g_cl[c0 + nj*8]        = lo0;
        *(uint32_t*)&g_ch[c0 + 8*DD + nj*8] = hi1;
        *(uint32_t*)&g_cl[c0 + 8*DD + nj*8] = lo1;
    }
}

// ============================================================
// attn normalization: attn = half(P) * (1/l)  -> fp32 out
// ============================================================
__global__ void fix_attn(float* __restrict__ attn)
{
    const int blk = blockIdx.x;
    const int bh = blk >> 11, row = blk & 2047;
    const float linv = 1.0f / g_ls[(size_t)bh*SS + row];
    const int t = threadIdx.x;
    const size_t base = ((size_t)bh*SS + row)*SS;
    uint4 raw = *(const uint4*)(g_ph + base + t*8);
    const __half2* hp = (const __half2*)&raw;
    float* dst = attn + base + t*8;
    float2 f0 = __half22float2(hp[0]);
    float2 f1 = __half22float2(hp[1]);
    float2 f2 = __half22float2(hp[2]);
    float2 f3 = __half22float2(hp[3]);
    float4 o0 = make_float4(f0.x*linv, f0.y*linv, f1.x*linv, f1.y*linv);
    float4 o1 = make_float4(f2.x*linv, f2.y*linv, f3.x*linv, f3.y*linv);
    *(float4*)(dst)     = o0;
    *(float4*)(dst + 4) = o1;
}

// ============================================================
// out = LayerNorm(pre + residual)
// ============================================================
__global__ void ln_kernel(const float* __restrict__ resid,
                          float* __restrict__ out)
{
    const size_t base = (size_t)blockIdx.x * DD;
    const int t = threadIdx.x;
    __shared__ float red1[8];
    __shared__ float red2[8];

    float v[4];
    float s = 0.f;
#pragma unroll
    for (int j = 0; j < 4; j++) {
        v[j] = g_pre[base + t + 256*j] + resid[base + t + 256*j];
        s += v[j];
    }
#pragma unroll
    for (int o = 16; o > 0; o >>= 1) s += __shfl_xor_sync(0xffffffffu, s, o);
    if ((t & 31) == 0) red1[t >> 5] = s;
    __syncthreads();
    s = red1[0];
#pragma unroll
    for (int w = 1; w < 8; w++) s += red1[w];
    const float mu = s * (1.0f / DD);

    float sq = 0.f;
#pragma unroll
    for (int j = 0; j < 4; j++) { const float d = v[j] - mu; sq += d*d; }
#pragma unroll
    for (int o = 16; o > 0; o >>= 1) sq += __shfl_xor_sync(0xffffffffu, sq, o);
    if ((t & 31) == 0) red2[t >> 5] = sq;
    __syncthreads();
    sq = red2[0];
#pragma unroll
    for (int w = 1; w < 8; w++) sq += red2[w];
    const float inv = rsqrtf(sq * (1.0f / DD) + 1e-5f);

#pragma unroll
    for (int j = 0; j < 4; j++) out[base + t + 256*j] = (v[j] - mu) * inv;
}

// ============================================================
extern "C" void kernel_launch(void* const* d_in, const int* in_sizes, int n_in,
                              void* d_out, int out_size)
{
    const float* inQ  = (const float*)d_in[0];
    const float* inK  = (const float*)d_in[1];
    const float* inV  = (const float*)d_in[2];
    const int*   mask = (const int*)  d_in[3];
    const float* WQ   = (const float*)d_in[4];
    const float* WK   = (const float*)d_in[5];
    const float* WV   = (const float*)d_in[6];
    const float* Wfc  = (const float*)d_in[7];
    float* out = (float*)d_out;

    bf16 *aqh, *aql, *akh, *akl, *avh, *avl;
    bf16 *wqh, *wql, *wkh, *wkl, *wvh, *wvl, *wfh, *wfl;
    bf16 *qh, *ql, *kh, *kl, *vh, *vl, *ch, *cl;
    float *ppre, *psc, *pdmy;
    cudaGetSymbolAddress((void**)&aqh, g_aqh); cudaGetSymbolAddress((void**)&aql, g_aql);
    cudaGetSymbolAddress((void**)&akh, g_akh); cudaGetSymbolAddress((void**)&akl, g_akl);
    cudaGetSymbolAddress((void**)&avh, g_avh); cudaGetSymbolAddress((void**)&avl, g_avl);
    cudaGetSymbolAddress((void**)&wqh, g_wqh); cudaGetSymbolAddress((void**)&wql, g_wql);
    cudaGetSymbolAddress((void**)&wkh, g_wkh); cudaGetSymbolAddress((void**)&wkl, g_wkl);
    cudaGetSymbolAddress((void**)&wvh, g_wvh); cudaGetSymbolAddress((void**)&wvl, g_wvl);
    cudaGetSymbolAddress((void**)&wfh, g_wfh); cudaGetSymbolAddress((void**)&wfl, g_wfl);
    cudaGetSymbolAddress((void**)&qh, g_qh);   cudaGetSymbolAddress((void**)&ql, g_ql);
    cudaGetSymbolAddress((void**)&kh, g_kh);   cudaGetSymbolAddress((void**)&kl, g_kl);
    cudaGetSymbolAddress((void**)&vh, g_vh);   cudaGetSymbolAddress((void**)&vl, g_vl);
    cudaGetSymbolAddress((void**)&ch, g_ch);   cudaGetSymbolAddress((void**)&cl, g_cl);
    cudaGetSymbolAddress((void**)&ppre, g_pre);
    cudaGetSymbolAddress((void**)&psc,  g_scores);
    cudaGetSymbolAddress((void**)&pdmy, g_dummy_out);

    const long long OUT_E  = (long long)NT * DD;
    const long long ATTN_E = (long long)BB * HH * SS * SS;

    float* out_dst  = out;
    float* attn_dst = psc;
    if ((long long)out_size >= OUT_E + ATTN_E) {
        attn_dst = out + OUT_E;
    } else if ((long long)out_size == ATTN_E) {
        attn_dst = out;
        out_dst  = pdmy;
    }

    cudaFuncSetAttribute(flash_attn, cudaFuncAttributeMaxDynamicSharedMemorySize, DYNSM_F);

    const dim3 blk(256);
    const int NACT = NT*DD/1024;
    const int NW   = DD*DD/1024;

    // pre-split inputs + weights
    presplit<<<NACT, blk>>>((const float4*)inQ, (uint2*)aqh, (uint2*)aql);
    presplit<<<NACT, blk>>>((const float4*)inK, (uint2*)akh, (uint2*)akl);
    presplit<<<NACT, blk>>>((const float4*)inV, (uint2*)avh, (uint2*)avl);
    presplit<<<NW,   blk>>>((const float4*)WQ,  (uint2*)wqh, (uint2*)wql);
    presplit<<<NW,   blk>>>((const float4*)WK,  (uint2*)wkh, (uint2*)wkl);
    presplit<<<NW,   blk>>>((const float4*)WV,  (uint2*)wvh, (uint2*)wvl);
    presplit<<<NW,   blk>>>((const float4*)Wfc, (uint2*)wfh, (uint2*)wfl);

    // projections -> split bf16 outputs
    gemm_mma_b<<<dim3(DD/128, NT/128), blk, DYNSM>>>(aqh, aql, wqh, wql, nullptr, qh, ql, DD, DD);
    gemm_mma_b<<<dim3(DD/128, NT/128), blk, DYNSM>>>(akh, akl, wkh, wkl, nullptr, kh, kl, DD, DD);
    gemm_mma_b<<<dim3(DD/128, NT/128), blk, DYNSM>>>(avh, avl, wvh, wvl, nullptr, vh, vl, DD, DD);

    // fused attention (P -> fp16 scratch; V plain bf16 in PV)
    flash_attn<<<dim3(16, BB*HH), blk, DYNSM_F>>>(mask);

    // normalize: fp16 P -> fp32 attn
    fix_attn<<<(unsigned)(BB*HH*SS), blk>>>(attn_dst);

    // output projection (fp32 out for LN)
    gemm_mma_b<<<dim3(DD/128, NT/128), blk, DYNSM>>>(ch, cl, wfh, wfl, ppre, nullptr, nullptr, DD, DD);

    // residual + layernorm
    ln_kernel<<<(unsigned)NT, blk>>>(inQ, out_dst);
}

// round 16
// speedup vs baseline: 1.2510x; 1.1003x over previous
#include <cuda_runtime.h>
#include <cuda_bf16.h>
#include <cuda_fp16.h>
#include <cstdint>
#include <math.h>

#define BB 2
#define SS 2048
#define DD 1024
#define HH 16
#define DK 64
#define NT (BB*SS)   // 4096 tokens

typedef __nv_bfloat16 bf16;

// ---- scratch (static device globals; no allocations) ----
__device__ bf16 g_aqh[(size_t)NT*DD], g_aql[(size_t)NT*DD];
__device__ bf16 g_akh[(size_t)NT*DD], g_akl[(size_t)NT*DD];
__device__ bf16 g_avh[(size_t)NT*DD], g_avl[(size_t)NT*DD];
__device__ bf16 g_wqh[(size_t)DD*DD], g_wql[(size_t)DD*DD];
__device__ bf16 g_wkh[(size_t)DD*DD], g_wkl[(size_t)DD*DD];
__device__ bf16 g_wvh[(size_t)DD*DD], g_wvl[(size_t)DD*DD];
__device__ bf16 g_wfh[(size_t)DD*DD], g_wfl[(size_t)DD*DD];
__device__ bf16 g_qh[(size_t)NT*DD], g_ql[(size_t)NT*DD];
__device__ bf16 g_kh[(size_t)NT*DD], g_kl[(size_t)NT*DD];
__device__ bf16 g_vh[(size_t)NT*DD];
__device__ bf16 g_ch[(size_t)NT*DD];
__device__ float g_pre[(size_t)NT*DD];
__device__ __half g_ph[(size_t)BB*HH*SS*SS];      // unnormalized P (fp16 scratch)
__device__ float g_scores[(size_t)BB*HH*SS*SS];   // fallback attn target only
__device__ float g_dummy_out[(size_t)NT*DD];
__device__ float g_ls[(size_t)32*SS];             // row sums

// ============================================================
// warp-MMA helpers (baseline PTX: sm_80+, no 'a' features)
// ============================================================
__device__ __forceinline__ uint32_t smem_u32(const void* p) {
    uint32_t a;
    asm("{ .reg .u64 t; cvta.to.shared.u64 t, %1; cvt.u32.u64 %0, t; }"
        : "=r"(a) : "l"(p));
    return a;
}
__device__ __forceinline__ void ldsm_x4(uint32_t* r, uint32_t addr) {
    asm volatile("ldmatrix.sync.aligned.m8n8.x4.shared.b16 {%0,%1,%2,%3}, [%4];"
        : "=r"(r[0]), "=r"(r[1]), "=r"(r[2]), "=r"(r[3]) : "r"(addr));
}
__device__ __forceinline__ void ldsm_x4_t(uint32_t* r, uint32_t addr) {
    asm volatile("ldmatrix.sync.aligned.m8n8.x4.trans.shared.b16 {%0,%1,%2,%3}, [%4];"
        : "=r"(r[0]), "=r"(r[1]), "=r"(r[2]), "=r"(r[3]) : "r"(addr));
}
__device__ __forceinline__ void mma_bf16(float* c, const uint32_t* a, const uint32_t* b) {
    asm volatile(
        "mma.sync.aligned.m16n8k16.row.col.f32.bf16.bf16.f32 "
        "{%0,%1,%2,%3}, {%4,%5,%6,%7}, {%8,%9}, {%0,%1,%2,%3};"
        : "+f"(c[0]), "+f"(c[1]), "+f"(c[2]), "+f"(c[3])
        : "r"(a[0]), "r"(a[1]), "r"(a[2]), "r"(a[3]), "r"(b[0]), "r"(b[1]));
}
__device__ __forceinline__ uint32_t packhl(float a, float b, uint32_t& lo) {
    __nv_bfloat162 hb = __float22bfloat162_rn(make_float2(a, b));
    float2 hf = __bfloat1622float2(hb);
    __nv_bfloat162 lb = __float22bfloat162_rn(make_float2(a - hf.x, b - hf.y));
    lo = *(uint32_t*)&lb;
    return *(uint32_t*)&hb;
}
__device__ __forceinline__ uint32_t pack2(float a, float b) {
    __nv_bfloat162 hb = __float22bfloat162_rn(make_float2(a, b));
    return *(uint32_t*)&hb;
}
__device__ __forceinline__ void stg_cs_u32(__half* p, uint32_t v) {
    asm volatile("st.global.cs.b32 [%0], %1;" :: "l"(p), "r"(v));
}

// ============================================================
// pre-split: fp32 tensor -> bf16 hi/lo
// ============================================================
__global__ void presplit(const float4* __restrict__ x,
                         uint2* __restrict__ hi, uint2* __restrict__ lo)
{
    const int i = blockIdx.x*blockDim.x + threadIdx.x;
    float4 v = x[i];
    __nv_bfloat162 h01 = __float22bfloat162_rn(make_float2(v.x, v.y));
    __nv_bfloat162 h23 = __float22bfloat162_rn(make_float2(v.z, v.w));
    float2 f01 = __bfloat1622float2(h01);
    float2 f23 = __bfloat1622float2(h23);
    __nv_bfloat162 l01 = __float22bfloat162_rn(make_float2(v.x - f01.x, v.y - f01.y));
    __nv_bfloat162 l23 = __float22bfloat162_rn(make_float2(v.z - f23.x, v.w - f23.y));
    hi[i] = make_uint2(*(uint32_t*)&h01, *(uint32_t*)&h23);
    lo[i] = make_uint2(*(uint32_t*)&l01, *(uint32_t*)&l23);
}
// plain convert: fp32 -> bf16 (no lo)
__global__ void preconv(const float4* __restrict__ x, uint2* __restrict__ hi)
{
    const int i = blockIdx.x*blockDim.x + threadIdx.x;
    float4 v = x[i];
    __nv_bfloat162 h01 = __float22bfloat162_rn(make_float2(v.x, v.y));
    __nv_bfloat162 h23 = __float22bfloat162_rn(make_float2(v.z, v.w));
    hi[i] = make_uint2(*(uint32_t*)&h01, *(uint32_t*)&h23);
}

// smem tile layout for split gemm (per buffer): Ah,Al,Bh,Bl each 128 rows x 48B
#define T_AH 0
#define T_AL 6144
#define T_BH 12288
#define T_BL 18432
#define BUFB 24576
#define DYNSM (2*BUFB)   // 48KB
// plain gemm: A,B tiles only
#define PBUF 12288
#define DYNSM_P (2*PBUF) // 24KB

__device__ __forceinline__ void mma_pass(float acc[2][8][4],
                                         uint32_t Af[2][4], uint32_t Bf[4][4])
{
#pragma unroll
    for (int ti = 0; ti < 2; ti++)
#pragma unroll
        for (int tj = 0; tj < 8; tj++)
            mma_bf16(acc[ti][tj], Af[ti], &Bf[tj >> 1][(tj & 1) * 2]);
}

// ============================================================
// 3-product split gemm: C[M,N] = A @ B^T (bf16 hi/lo io)
// ============================================================
__global__ __launch_bounds__(256, 2)
void gemm_mma_b(const bf16* __restrict__ Ah, const bf16* __restrict__ Al,
                const bf16* __restrict__ Bh, const bf16* __restrict__ Bl,
                bf16* __restrict__ Ch, bf16* __restrict__ Cl,
                int N, int K)
{
    extern __shared__ __align__(128) char sm[];
    const uint32_t smb = smem_u32(sm);
    const int t = threadIdx.x;
    const int lane = t & 31, warp = t >> 5;
    const int wm = warp >> 1, wn = warp & 1;
    const int i0 = blockIdx.y * 128, j0 = blockIdx.x * 128;

    float acc[2][8][4];
#pragma unroll
    for (int a = 0; a < 2; a++)
#pragma unroll
        for (int b = 0; b < 8; b++)
#pragma unroll
            for (int c = 0; c < 4; c++) acc[a][b][c] = 0.f;

    const int r = t >> 1, kc = (t & 1) * 8;
    const int stoff = r * 48 + (t & 1) * 16;
    const bf16* pAh = Ah + (size_t)(i0 + r) * K + kc;
    const bf16* pAl = Al + (size_t)(i0 + r) * K + kc;
    const bf16* pBh = Bh + (size_t)(j0 + r) * K + kc;
    const bf16* pBl = Bl + (size_t)(j0 + r) * K + kc;

    const uint32_t a_off = (uint32_t)((wm*32 + (lane & 15)) * 48 + ((lane >> 4) & 1) * 16);
    const uint32_t b_off = (uint32_t)((wn*64 + (lane & 7) + ((lane >> 4) & 1) * 8) * 48
                                      + ((lane >> 3) & 1) * 16);

    *(uint4*)(sm + T_AH + stoff) = *(const uint4*)pAh;
    *(uint4*)(sm + T_AL + stoff) = *(const uint4*)pAl;
    *(uint4*)(sm + T_BH + stoff) = *(const uint4*)pBh;
    *(uint4*)(sm + T_BL + stoff) = *(const uint4*)pBl;
    __syncthreads();

    const int nst = K / 16;
    for (int s = 0; s < nst; s++) {
        const int buf = (s & 1) * BUFB;
        const bool more = (s + 1 < nst);
        uint4 nA, nAl, nB, nBl;
        if (more) {
            nA  = *(const uint4*)(pAh + (s+1)*16);
            nAl = *(const uint4*)(pAl + (s+1)*16);
            nB  = *(const uint4*)(pBh + (s+1)*16);
            nBl = *(const uint4*)(pBl + (s+1)*16);
        }
        uint32_t Af[2][4], Bf[4][4], X[4][4];
#pragma unroll
        for (int ti = 0; ti < 2; ti++)
            ldsm_x4(Af[ti], smb + buf + T_AH + a_off + ti*16*48);
#pragma unroll
        for (int pj = 0; pj < 4; pj++)
            ldsm_x4(Bf[pj], smb + buf + T_BH + b_off + pj*16*48);
        mma_pass(acc, Af, Bf);
#pragma unroll
        for (int pj = 0; pj < 4; pj++)
            ldsm_x4(X[pj], smb + buf + T_BL + b_off + pj*16*48);
        mma_pass(acc, Af, X);
#pragma unroll
        for (int ti = 0; ti < 2; ti++)
            ldsm_x4(X[ti], smb + buf + T_AL + a_off + ti*16*48);
        mma_pass(acc, X, Bf);

        if (more) {
            __syncthreads();
            const int nb = buf ^ BUFB;
            *(uint4*)(sm + nb + T_AH + stoff) = nA;
            *(uint4*)(sm + nb + T_AL + stoff) = nAl;
            *(uint4*)(sm + nb + T_BH + stoff) = nB;
            *(uint4*)(sm + nb + T_BL + stoff) = nBl;
            __syncthreads();
        }
    }

    const int rb = i0 + wm*32 + (lane >> 2);
    const int cb = j0 + wn*64 + (lane & 3) * 2;
#pragma unroll
    for (int ti = 0; ti < 2; ti++)
#pragma unroll
        for (int tj = 0; tj < 8; tj++) {
            const int i = rb + ti*16, j = cb + tj*8;
            uint32_t lo0, lo1;
            uint32_t hi0 = packhl(acc[ti][tj][0], acc[ti][tj][1], lo0);
            uint32_t hi1 = packhl(acc[ti][tj][2], acc[ti][tj][3], lo1);
            *(uint32_t*)&Ch[(size_t)i*N + j]     = hi0;
            *(uint32_t*)&Cl[(size_t)i*N + j]     = lo0;
            *(uint32_t*)&Ch[(size_t)(i+8)*N + j] = hi1;
            *(uint32_t*)&Cl[(size_t)(i+8)*N + j] = lo1;
        }
}

// ============================================================
// plain bf16 gemm (1 product): out-path tolerant (V proj, FC)
// ============================================================
__global__ __launch_bounds__(256, 2)
void gemm_plain(const bf16* __restrict__ Ah, const bf16* __restrict__ Bh,
                float* __restrict__ Cf, bf16* __restrict__ Ch,
                int N, int K)
{
    extern __shared__ __align__(128) char sm[];
    const uint32_t smb = smem_u32(sm);
    const int t = threadIdx.x;
    const int lane = t & 31, warp = t >> 5;
    const int wm = warp >> 1, wn = warp & 1;
    const int i0 = blockIdx.y * 128, j0 = blockIdx.x * 128;

    float acc[2][8][4];
#pragma unroll
    for (int a = 0; a < 2; a++)
#pragma unroll
        for (int b = 0; b < 8; b++)
#pragma unroll
            for (int c = 0; c < 4; c++) acc[a][b][c] = 0.f;

    const int r = t >> 1, kc = (t & 1) * 8;
    const int stoff = r * 48 + (t & 1) * 16;
    const bf16* pAh = Ah + (size_t)(i0 + r) * K + kc;
    const bf16* pBh = Bh + (size_t)(j0 + r) * K + kc;

    const uint32_t a_off = (uint32_t)((wm*32 + (lane & 15)) * 48 + ((lane >> 4) & 1) * 16);
    const uint32_t b_off = (uint32_t)((wn*64 + (lane & 7) + ((lane >> 4) & 1) * 8) * 48
                                      + ((lane >> 3) & 1) * 16);

    *(uint4*)(sm + stoff)        = *(const uint4*)pAh;
    *(uint4*)(sm + 6144 + stoff) = *(const uint4*)pBh;
    __syncthreads();

    const int nst = K / 16;
    for (int s = 0; s < nst; s++) {
        const int buf = (s & 1) * PBUF;
        const bool more = (s + 1 < nst);
        uint4 nA, nB;
        if (more) {
            nA = *(const uint4*)(pAh + (s+1)*16);
            nB = *(const uint4*)(pBh + (s+1)*16);
        }
        uint32_t Af[2][4], Bf[4][4];
#pragma unroll
        for (int ti = 0; ti < 2; ti++)
            ldsm_x4(Af[ti], smb + buf + a_off + ti*16*48);
#pragma unroll
        for (int pj = 0; pj < 4; pj++)
            ldsm_x4(Bf[pj], smb + buf + 6144 + b_off + pj*16*48);
        mma_pass(acc, Af, Bf);

        if (more) {
            __syncthreads();
            const int nb = buf ^ PBUF;
            *(uint4*)(sm + nb + stoff)        = nA;
            *(uint4*)(sm + nb + 6144 + stoff) = nB;
            __syncthreads();
        }
    }

    const int rb = i0 + wm*32 + (lane >> 2);
    const int cb = j0 + wn*64 + (lane & 3) * 2;
    if (Cf) {
#pragma unroll
        for (int ti = 0; ti < 2; ti++)
#pragma unroll
            for (int tj = 0; tj < 8; tj++) {
                const int i = rb + ti*16, j = cb + tj*8;
                *(float2*)&Cf[(size_t)i*N + j]     = make_float2(acc[ti][tj][0], acc[ti][tj][1]);
                *(float2*)&Cf[(size_t)(i+8)*N + j] = make_float2(acc[ti][tj][2], acc[ti][tj][3]);
            }
    } else {
#pragma unroll
        for (int ti = 0; ti < 2; ti++)
#pragma unroll
            for (int tj = 0; tj < 8; tj++) {
                const int i = rb + ti*16, j = cb + tj*8;
                *(uint32_t*)&Ch[(size_t)i*N + j]     = pack2(acc[ti][tj][0], acc[ti][tj][1]);
                *(uint32_t*)&Ch[(size_t)(i+8)*N + j] = pack2(acc[ti][tj][2], acc[ti][tj][3]);
            }
    }
}

// ============================================================
// fused flash attention: j-tile 64, 2 CTAs/SM.
// V plain bf16 in PV; P hi/lo; ctx out plain bf16.
// ============================================================
#define KST 144
#define FBUF 27648
#define FKH(b) ((b)*FBUF)
#define FKL(b) ((b)*FBUF + 9216)
#define FVH(b) ((b)*FBUF + 18432)
#define DYNSM_F 55296

__device__ __forceinline__ void stage_kv64_b(char* sm, int hOff, int lOff,
                                             const bf16* srcH, const bf16* srcL, int t)
{
    const int row = t >> 2, ch = t & 3;
    const size_t g = (size_t)row*DD + ch*16;
    const int so = row*KST + ch*32;
    *(uint4*)(sm + hOff + so)      = *(const uint4*)(srcH + g);
    *(uint4*)(sm + hOff + so + 16) = *(const uint4*)(srcH + g + 8);
    *(uint4*)(sm + lOff + so)      = *(const uint4*)(srcL + g);
    *(uint4*)(sm + lOff + so + 16) = *(const uint4*)(srcL + g + 8);
}
__device__ __forceinline__ void stage_v64(char* sm, int hOff,
                                          const bf16* srcH, int t)
{
    const int row = t >> 2, ch = t & 3;
    const size_t g = (size_t)row*DD + ch*16;
    const int so = row*KST + ch*32;
    *(uint4*)(sm + hOff + so)      = *(const uint4*)(srcH + g);
    *(uint4*)(sm + hOff + so + 16) = *(const uint4*)(srcH + g + 8);
}
__device__ __forceinline__ void stage_q128_b(char* sm, int hOff, int lOff,
                                             const bf16* srcH, const bf16* srcL, int t)
{
    const int row = t >> 1, half = t & 1;
    const size_t g = (size_t)row*DD + half*32;
    const int so = row*KST + half*64;
#pragma unroll
    for (int q = 0; q < 4; q++) {
        *(uint4*)(sm + hOff + so + q*16) = *(const uint4*)(srcH + g + q*8);
        *(uint4*)(sm + lOff + so + q*16) = *(const uint4*)(srcL + g + q*8);
    }
}

__global__ __launch_bounds__(256, 2)
void flash_attn(const int* __restrict__ mask)
{
    extern __shared__ __align__(128) char sm[];
    const uint32_t smb = smem_u32(sm);
    const int t = threadIdx.x;
    const int lane = t & 31, w = t >> 5;
    const int rbk = blockIdx.x, bh = blockIdx.y;
    const int b = bh >> 4, h = bh & 15;
    const int i0 = rbk * 128;

    const size_t qoff = ((size_t)b*SS + i0)*DD + h*DK;
    const size_t koff = (size_t)b*SS*DD + h*DK;

    stage_q128_b(sm, 0, 18432, g_qh + qoff, g_ql + qoff, t);
    __syncthreads();

    uint32_t Qh[4][4], Ql[4][4];
    {
        const uint32_t a_base = (uint32_t)((w*16 + (lane & 15))*KST + ((lane >> 4) & 1)*16);
#pragma unroll
        for (int c = 0; c < 4; c++) {
            ldsm_x4(Qh[c], smb + a_base + c*32);
            ldsm_x4(Ql[c], smb + 18432 + a_base + c*32);
        }
    }
    __syncthreads();

    stage_kv64_b(sm, FKH(0), FKL(0), g_kh + koff, g_kl + koff, t);
    stage_v64(sm, FVH(0), g_vh + koff, t);
    __syncthreads();

    float accO[8][4];
#pragma unroll
    for (int a = 0; a < 8; a++)
#pragma unroll
        for (int c = 0; c < 4; c++) accO[a][c] = 0.f;
    float lrun[2] = {0.f, 0.f};

    const int* mb = mask + (size_t)b*SS*SS;
    __half* prow = g_ph + (size_t)bh*SS*SS;
    const int r0l = w*16 + (lane >> 2);
    const int qrow = lane & 3;
    const int gi0 = i0 + r0l;

    const uint32_t kb_base = (uint32_t)(((lane & 7) + ((lane >> 4) & 1)*8)*KST
                                        + ((lane >> 3) & 1)*16);
    const uint32_t vb_base = (uint32_t)(((lane & 7) + ((lane >> 3) & 1)*8)*KST
                                        + ((lane >> 4) & 1)*16);

    for (int jt = 0; jt < 32; jt++) {
        const int buf = jt & 1;
        if (jt + 1 < 32) {
            const size_t nk = koff + (size_t)(jt+1)*64*DD;
            stage_kv64_b(sm, FKH(buf^1), FKL(buf^1), g_kh + nk, g_kl + nk, t);
            stage_v64(sm, FVH(buf^1), g_vh + nk, t);
        }

        // ---- S = Q K^T (3-product split) ----
        float accS[8][4];
#pragma unroll
        for (int a = 0; a < 8; a++)
#pragma unroll
            for (int c = 0; c < 4; c++) accS[a][c] = 0.f;
#pragma unroll
        for (int c = 0; c < 4; c++) {
#pragma unroll
            for (int jg = 0; jg < 4; jg++) {
                uint32_t Kh4[4], Kl4[4];
                const uint32_t ko = kb_base + (uint32_t)(jg*16*KST + c*32);
                ldsm_x4(Kh4, smb + FKH(buf) + ko);
                ldsm_x4(Kl4, smb + FKL(buf) + ko);
                mma_bf16(accS[2*jg],   Qh[c], Kh4);
                mma_bf16(accS[2*jg+1], Qh[c], Kh4 + 2);
                mma_bf16(accS[2*jg],   Ql[c], Kh4);
                mma_bf16(accS[2*jg+1], Ql[c], Kh4 + 2);
                mma_bf16(accS[2*jg],   Qh[c], Kl4);
                mma_bf16(accS[2*jg+1], Qh[c], Kl4 + 2);
            }
        }

        // ---- mask + scale + exp + row-sum ----
        float es0 = 0.f, es1 = 0.f;
#pragma unroll
        for (int tj = 0; tj < 8; tj++) {
            const int j = jt*64 + tj*8 + qrow*2;
            int2 m0 = *(const int2*)&mb[(size_t)gi0*SS + j];
            int2 m1 = *(const int2*)&mb[(size_t)(gi0+8)*SS + j];
            float e0 = m0.x ? 0.f : __expf(accS[tj][0]*0.125f);
            float e1 = m0.y ? 0.f : __expf(accS[tj][1]*0.125f);
            float e2 = m1.x ? 0.f : __expf(accS[tj][2]*0.125f);
            float e3 = m1.y ? 0.f : __expf(accS[tj][3]*0.125f);
            accS[tj][0] = e0; accS[tj][1] = e1;
            accS[tj][2] = e2; accS[tj][3] = e3;
            es0 += e0 + e1;
            es1 += e2 + e3;
        }
        es0 += __shfl_xor_sync(0xffffffffu, es0, 1);
        es0 += __shfl_xor_sync(0xffffffffu, es0, 2);
        es1 += __shfl_xor_sync(0xffffffffu, es1, 1);
        es1 += __shfl_xor_sync(0xffffffffu, es1, 2);
        lrun[0] += es0;
        lrun[1] += es1;

        // ---- write unnormalized P as fp16 (streaming stores) ----
#pragma unroll
        for (int tj = 0; tj < 8; tj++) {
            const int j = jt*64 + tj*8 + qrow*2;
            __half2 p0 = __floats2half2_rn(accS[tj][0], accS[tj][1]);
            __half2 p1 = __floats2half2_rn(accS[tj][2], accS[tj][3]);
            stg_cs_u32(&prow[(size_t)gi0*SS + j],     *(uint32_t*)&p0);
            stg_cs_u32(&prow[(size_t)(gi0+8)*SS + j], *(uint32_t*)&p1);
        }

        // ---- O += P @ V (P hi/lo x V bf16: 2 products) ----
#pragma unroll
        for (int q = 0; q < 4; q++) {
            uint32_t ah[4], al[4];
            ah[0] = packhl(accS[2*q][0],   accS[2*q][1],   al[0]);
            ah[1] = packhl(accS[2*q][2],   accS[2*q][3],   al[1]);
            ah[2] = packhl(accS[2*q+1][0], accS[2*q+1][1], al[2]);
            ah[3] = packhl(accS[2*q+1][2], accS[2*q+1][3], al[3]);
#pragma unroll
            for (int vg = 0; vg < 4; vg++) {
                uint32_t Vh4[4];
                const uint32_t vo = vb_base + (uint32_t)(q*16*KST + vg*32);
                ldsm_x4_t(Vh4, smb + FVH(buf) + vo);
                mma_bf16(accO[2*vg],   ah, Vh4);
                mma_bf16(accO[2*vg+1], ah, Vh4 + 2);
                mma_bf16(accO[2*vg],   al, Vh4);
                mma_bf16(accO[2*vg+1], al, Vh4 + 2);
            }
        }
        __syncthreads();
    }

    // ---- finalize: row sums + ctx written as plain bf16 ----
    if ((lane & 3) == 0) {
        g_ls[(size_t)bh*SS + gi0]     = lrun[0];
        g_ls[(size_t)bh*SS + gi0 + 8] = lrun[1];
    }
    const float rl0 = 1.f / lrun[0];
    const float rl1 = 1.f / lrun[1];
    const size_t c0 = ((size_t)b*SS + gi0)*DD + h*DK + qrow*2;
#pragma unroll
    for (int nj = 0; nj < 8; nj++) {
        *(uint32_t*)&g_ch[c0 + nj*8]        = pack2(accO[nj][0]*rl0, accO[nj][1]*rl0);
        *(uint32_t*)&g_ch[c0 + 8*DD + nj*8] = pack2(accO[nj][2]*rl1, accO[nj][3]*rl1);
    }
}

// ============================================================
// attn normalization: attn = half(P) * (1/l)  -> fp32 out
// ============================================================
__global__ void fix_attn(float* __restrict__ attn)
{
    const int blk = blockIdx.x;
    const int bh = blk >> 11, row = blk & 2047;
    const float linv = 1.0f / g_ls[(size_t)bh*SS + row];
    const int t = threadIdx.x;
    const size_t base = ((size_t)bh*SS + row)*SS;
    uint4 raw = *(const uint4*)(g_ph + base + t*8);
    const __half2* hp = (const __half2*)&raw;
    float* dst = attn + base + t*8;
    float2 f0 = __half22float2(hp[0]);
    float2 f1 = __half22float2(hp[1]);
    float2 f2 = __half22float2(hp[2]);
    float2 f3 = __half22float2(hp[3]);
    float4 o0 = make_float4(f0.x*linv, f0.y*linv, f1.x*linv, f1.y*linv);
    float4 o1 = make_float4(f2.x*linv, f2.y*linv, f3.x*linv, f3.y*linv);
    *(float4*)(dst)     = o0;
    *(float4*)(dst + 4) = o1;
}

// ============================================================
// out = LayerNorm(pre + residual)
// ============================================================
__global__ void ln_kernel(const float* __restrict__ resid,
                          float* __restrict__ out)
{
    const size_t base = (size_t)blockIdx.x * DD;
    const int t = threadIdx.x;
    __shared__ float red1[8];
    __shared__ float red2[8];

    float v[4];
    float s = 0.f;
#pragma unroll
    for (int j = 0; j < 4; j++) {
        v[j] = g_pre[base + t + 256*j] + resid[base + t + 256*j];
        s += v[j];
    }
#pragma unroll
    for (int o = 16; o > 0; o >>= 1) s += __shfl_xor_sync(0xffffffffu, s, o);
    if ((t & 31) == 0) red1[t >> 5] = s;
    __syncthreads();
    s = red1[0];
#pragma unroll
    for (int w = 1; w < 8; w++) s += red1[w];
    const float mu = s * (1.0f / DD);

    float sq = 0.f;
#pragma unroll
    for (int j = 0; j < 4; j++) { const float d = v[j] - mu; sq += d*d; }
#pragma unroll
    for (int o = 16; o > 0; o >>= 1) sq += __shfl_xor_sync(0xffffffffu, sq, o);
    if ((t & 31) == 0) red2[t >> 5] = sq;
    __syncthreads();
    sq = red2[0];
#pragma unroll
    for (int w = 1; w < 8; w++) sq += red2[w];
    const float inv = rsqrtf(sq * (1.0f / DD) + 1e-5f);

#pragma unroll
    for (int j = 0; j < 4; j++) out[base + t + 256*j] = (v[j] - mu) * inv;
}

// ============================================================
extern "C" void kernel_launch(void* const* d_in, const int* in_sizes, int n_in,
                              void* d_out, int out_size)
{
    const float* inQ  = (const float*)d_in[0];
    const float* inK  = (const float*)d_in[1];
    const float* inV  = (const float*)d_in[2];
    const int*   mask = (const int*)  d_in[3];
    const float* WQ   = (const float*)d_in[4];
    const float* WK   = (const float*)d_in[5];
    const float* WV   = (const float*)d_in[6];
    const float* Wfc  = (const float*)d_in[7];
    float* out = (float*)d_out;

    bf16 *aqh, *aql, *akh, *akl, *avh;
    bf16 *wqh, *wql, *wkh, *wkl, *wvh, *wfh;
    bf16 *qh, *ql, *kh, *kl, *vh, *ch;
    float *ppre, *psc, *pdmy;
    cudaGetSymbolAddress((void**)&aqh, g_aqh); cudaGetSymbolAddress((void**)&aql, g_aql);
    cudaGetSymbolAddress((void**)&akh, g_akh); cudaGetSymbolAddress((void**)&akl, g_akl);
    cudaGetSymbolAddress((void**)&avh, g_avh);
    cudaGetSymbolAddress((void**)&wqh, g_wqh); cudaGetSymbolAddress((void**)&wql, g_wql);
    cudaGetSymbolAddress((void**)&wkh, g_wkh); cudaGetSymbolAddress((void**)&wkl, g_wkl);
    cudaGetSymbolAddress((void**)&wvh, g_wvh);
    cudaGetSymbolAddress((void**)&wfh, g_wfh);
    cudaGetSymbolAddress((void**)&qh, g_qh);   cudaGetSymbolAddress((void**)&ql, g_ql);
    cudaGetSymbolAddress((void**)&kh, g_kh);   cudaGetSymbolAddress((void**)&kl, g_kl);
    cudaGetSymbolAddress((void**)&vh, g_vh);
    cudaGetSymbolAddress((void**)&ch, g_ch);
    cudaGetSymbolAddress((void**)&ppre, g_pre);
    cudaGetSymbolAddress((void**)&psc,  g_scores);
    cudaGetSymbolAddress((void**)&pdmy, g_dummy_out);

    const long long OUT_E  = (long long)NT * DD;
    const long long ATTN_E = (long long)BB * HH * SS * SS;

    float* out_dst  = out;
    float* attn_dst = psc;
    if ((long long)out_size >= OUT_E + ATTN_E) {
        attn_dst = out + OUT_E;
    } else if ((long long)out_size == ATTN_E) {
        attn_dst = out;
        out_dst  = pdmy;
    }

    cudaFuncSetAttribute(flash_attn, cudaFuncAttributeMaxDynamicSharedMemorySize, DYNSM_F);

    const dim3 blk(256);
    const int NACT = NT*DD/1024;
    const int NW   = DD*DD/1024;

    // pre-split Q/K paths (hi/lo); plain convert for V and FC paths
    presplit<<<NACT, blk>>>((const float4*)inQ, (uint2*)aqh, (uint2*)aql);
    presplit<<<NACT, blk>>>((const float4*)inK, (uint2*)akh, (uint2*)akl);
    preconv<<<NACT, blk>>>((const float4*)inV, (uint2*)avh);
    presplit<<<NW,   blk>>>((const float4*)WQ,  (uint2*)wqh, (uint2*)wql);
    presplit<<<NW,   blk>>>((const float4*)WK,  (uint2*)wkh, (uint2*)wkl);
    preconv<<<NW,   blk>>>((const float4*)WV,  (uint2*)wvh);
    preconv<<<NW,   blk>>>((const float4*)Wfc, (uint2*)wfh);

    // Q/K projections: 3-product split (feed exp)
    gemm_mma_b<<<dim3(DD/128, NT/128), blk, DYNSM>>>(aqh, aql, wqh, wql, qh, ql, DD, DD);
    gemm_mma_b<<<dim3(DD/128, NT/128), blk, DYNSM>>>(akh, akl, wkh, wkl, kh, kl, DD, DD);
    // V projection: plain bf16 (out-path tolerant)
    gemm_plain<<<dim3(DD/128, NT/128), blk, DYNSM_P>>>(avh, wvh, nullptr, vh, DD, DD);

    // fused attention (P -> fp16 scratch; V plain bf16; ctx plain bf16)
    flash_attn<<<dim3(16, BB*HH), blk, DYNSM_F>>>(mask);

    // normalize: fp16 P -> fp32 attn
    fix_attn<<<(unsigned)(BB*HH*SS), blk>>>(attn_dst);

    // output projection: plain bf16 (out-path tolerant), fp32 out for LN
    gemm_plain<<<dim3(DD/128, NT/128), blk, DYNSM_P>>>(ch, wfh, ppre, nullptr, DD, DD);

    // residual + layernorm
    ln_kernel<<<(unsigned)NT, blk>>>(inQ, out_dst);
}

// round 17
// speedup vs baseline: 1.2741x; 1.0185x over previous
#include <cuda_runtime.h>
#include <cuda_bf16.h>
#include <cuda_fp16.h>
#include <cstdint>
#include <math.h>

#define BB 2
#define SS 2048
#define DD 1024
#define HH 16
#define DK 64
#define NT (BB*SS)   // 4096 tokens

typedef __nv_bfloat16 bf16;

// ---- scratch (static device globals; no allocations) ----
__device__ bf16 g_aqh[(size_t)NT*DD], g_aql[(size_t)NT*DD];
__device__ bf16 g_akh[(size_t)NT*DD], g_akl[(size_t)NT*DD];
__device__ bf16 g_avh[(size_t)NT*DD];
__device__ bf16 g_wqh[(size_t)DD*DD], g_wql[(size_t)DD*DD];
__device__ bf16 g_wkh[(size_t)DD*DD], g_wkl[(size_t)DD*DD];
__device__ bf16 g_wvh[(size_t)DD*DD];
__device__ bf16 g_wfh[(size_t)DD*DD];
__device__ bf16 g_qh[(size_t)NT*DD], g_ql[(size_t)NT*DD];
__device__ bf16 g_kh[(size_t)NT*DD], g_kl[(size_t)NT*DD];
__device__ bf16 g_vh[(size_t)NT*DD];
__device__ bf16 g_ch[(size_t)NT*DD];
__device__ float g_pre[(size_t)NT*DD];
__device__ __half g_ph[(size_t)BB*HH*SS*SS];      // unnormalized P (fp16 scratch)
__device__ float g_scores[(size_t)BB*HH*SS*SS];   // fallback attn target only
__device__ float g_dummy_out[(size_t)NT*DD];
__device__ float g_ls[(size_t)32*SS];             // row sums

// ============================================================
// warp-MMA + cp.async helpers (baseline PTX: sm_80+)
// ============================================================
__device__ __forceinline__ uint32_t smem_u32(const void* p) {
    uint32_t a;
    asm("{ .reg .u64 t; cvta.to.shared.u64 t, %1; cvt.u32.u64 %0, t; }"
        : "=r"(a) : "l"(p));
    return a;
}
__device__ __forceinline__ void cp16(uint32_t s, const void* g) {
    asm volatile("cp.async.cg.shared.global [%0], [%1], 16;" :: "r"(s), "l"(g));
}
__device__ __forceinline__ void cp_commit() {
    asm volatile("cp.async.commit_group;" ::: "memory");
}
__device__ __forceinline__ void cp_wait0() {
    asm volatile("cp.async.wait_group 0;" ::: "memory");
}
__device__ __forceinline__ void ldsm_x4(uint32_t* r, uint32_t addr) {
    asm volatile("ldmatrix.sync.aligned.m8n8.x4.shared.b16 {%0,%1,%2,%3}, [%4];"
        : "=r"(r[0]), "=r"(r[1]), "=r"(r[2]), "=r"(r[3]) : "r"(addr));
}
__device__ __forceinline__ void ldsm_x4_t(uint32_t* r, uint32_t addr) {
    asm volatile("ldmatrix.sync.aligned.m8n8.x4.trans.shared.b16 {%0,%1,%2,%3}, [%4];"
        : "=r"(r[0]), "=r"(r[1]), "=r"(r[2]), "=r"(r[3]) : "r"(addr));
}
__device__ __forceinline__ void mma_bf16(float* c, const uint32_t* a, const uint32_t* b) {
    asm volatile(
        "mma.sync.aligned.m16n8k16.row.col.f32.bf16.bf16.f32 "
        "{%0,%1,%2,%3}, {%4,%5,%6,%7}, {%8,%9}, {%0,%1,%2,%3};"
        : "+f"(c[0]), "+f"(c[1]), "+f"(c[2]), "+f"(c[3])
        : "r"(a[0]), "r"(a[1]), "r"(a[2]), "r"(a[3]), "r"(b[0]), "r"(b[1]));
}
__device__ __forceinline__ uint32_t packhl(float a, float b, uint32_t& lo) {
    __nv_bfloat162 hb = __float22bfloat162_rn(make_float2(a, b));
    float2 hf = __bfloat1622float2(hb);
    __nv_bfloat162 lb = __float22bfloat162_rn(make_float2(a - hf.x, b - hf.y));
    lo = *(uint32_t*)&lb;
    return *(uint32_t*)&hb;
}
__device__ __forceinline__ uint32_t pack2(float a, float b) {
    __nv_bfloat162 hb = __float22bfloat162_rn(make_float2(a, b));
    return *(uint32_t*)&hb;
}
__device__ __forceinline__ void stg_cs_u32(__half* p, uint32_t v) {
    asm volatile("st.global.cs.b32 [%0], %1;" :: "l"(p), "r"(v));
}

// ============================================================
// pre-split: fp32 tensor -> bf16 hi/lo
// ============================================================
__global__ void presplit(const float4* __restrict__ x,
                         uint2* __restrict__ hi, uint2* __restrict__ lo)
{
    const int i = blockIdx.x*blockDim.x + threadIdx.x;
    float4 v = x[i];
    __nv_bfloat162 h01 = __float22bfloat162_rn(make_float2(v.x, v.y));
    __nv_bfloat162 h23 = __float22bfloat162_rn(make_float2(v.z, v.w));
    float2 f01 = __bfloat1622float2(h01);
    float2 f23 = __bfloat1622float2(h23);
    __nv_bfloat162 l01 = __float22bfloat162_rn(make_float2(v.x - f01.x, v.y - f01.y));
    __nv_bfloat162 l23 = __float22bfloat162_rn(make_float2(v.z - f23.x, v.w - f23.y));
    hi[i] = make_uint2(*(uint32_t*)&h01, *(uint32_t*)&h23);
    lo[i] = make_uint2(*(uint32_t*)&l01, *(uint32_t*)&l23);
}
// plain convert: fp32 -> bf16 (no lo)
__global__ void preconv(const float4* __restrict__ x, uint2* __restrict__ hi)
{
    const int i = blockIdx.x*blockDim.x + threadIdx.x;
    float4 v = x[i];
    __nv_bfloat162 h01 = __float22bfloat162_rn(make_float2(v.x, v.y));
    __nv_bfloat162 h23 = __float22bfloat162_rn(make_float2(v.z, v.w));
    hi[i] = make_uint2(*(uint32_t*)&h01, *(uint32_t*)&h23);
}

// smem tile layout for split gemm (per buffer): Ah,Al,Bh,Bl each 128 rows x 48B
#define T_AH 0
#define T_AL 6144
#define T_BH 12288
#define T_BL 18432
#define BUFB 24576
#define DYNSM (2*BUFB)   // 48KB
// plain gemm: A,B tiles only
#define PBUF 12288
#define DYNSM_P (2*PBUF) // 24KB

__device__ __forceinline__ void mma_pass(float acc[2][8][4],
                                         uint32_t Af[2][4], uint32_t Bf[4][4])
{
#pragma unroll
    for (int ti = 0; ti < 2; ti++)
#pragma unroll
        for (int tj = 0; tj < 8; tj++)
            mma_bf16(acc[ti][tj], Af[ti], &Bf[tj >> 1][(tj & 1) * 2]);
}

// ============================================================
// 3-product split gemm: C[M,N] = A @ B^T (bf16 hi/lo io)
// ============================================================
__global__ __launch_bounds__(256, 2)
void gemm_mma_b(const bf16* __restrict__ Ah, const bf16* __restrict__ Al,
                const bf16* __restrict__ Bh, const bf16* __restrict__ Bl,
                bf16* __restrict__ Ch, bf16* __restrict__ Cl,
                int N, int K)
{
    extern __shared__ __align__(128) char sm[];
    const uint32_t smb = smem_u32(sm);
    const int t = threadIdx.x;
    const int lane = t & 31, warp = t >> 5;
    const int wm = warp >> 1, wn = warp & 1;
    const int i0 = blockIdx.y * 128, j0 = blockIdx.x * 128;

    float acc[2][8][4];
#pragma unroll
    for (int a = 0; a < 2; a++)
#pragma unroll
        for (int b = 0; b < 8; b++)
#pragma unroll
            for (int c = 0; c < 4; c++) acc[a][b][c] = 0.f;

    const int r = t >> 1, kc = (t & 1) * 8;
    const int stoff = r * 48 + (t & 1) * 16;
    const bf16* pAh = Ah + (size_t)(i0 + r) * K + kc;
    const bf16* pAl = Al + (size_t)(i0 + r) * K + kc;
    const bf16* pBh = Bh + (size_t)(j0 + r) * K + kc;
    const bf16* pBl = Bl + (size_t)(j0 + r) * K + kc;

    const uint32_t a_off = (uint32_t)((wm*32 + (lane & 15)) * 48 + ((lane >> 4) & 1) * 16);
    const uint32_t b_off = (uint32_t)((wn*64 + (lane & 7) + ((lane >> 4) & 1) * 8) * 48
                                      + ((lane >> 3) & 1) * 16);

    *(uint4*)(sm + T_AH + stoff) = *(const uint4*)pAh;
    *(uint4*)(sm + T_AL + stoff) = *(const uint4*)pAl;
    *(uint4*)(sm + T_BH + stoff) = *(const uint4*)pBh;
    *(uint4*)(sm + T_BL + stoff) = *(const uint4*)pBl;
    __syncthreads();

    const int nst = K / 16;
    for (int s = 0; s < nst; s++) {
        const int buf = (s & 1) * BUFB;
        const bool more = (s + 1 < nst);
        uint4 nA, nAl, nB, nBl;
        if (more) {
            nA  = *(const uint4*)(pAh + (s+1)*16);
            nAl = *(const uint4*)(pAl + (s+1)*16);
            nB  = *(const uint4*)(pBh + (s+1)*16);
            nBl = *(const uint4*)(pBl + (s+1)*16);
        }
        uint32_t Af[2][4], Bf[4][4], X[4][4];
#pragma unroll
        for (int ti = 0; ti < 2; ti++)
            ldsm_x4(Af[ti], smb + buf + T_AH + a_off + ti*16*48);
#pragma unroll
        for (int pj = 0; pj < 4; pj++)
            ldsm_x4(Bf[pj], smb + buf + T_BH + b_off + pj*16*48);
        mma_pass(acc, Af, Bf);
#pragma unroll
        for (int pj = 0; pj < 4; pj++)
            ldsm_x4(X[pj], smb + buf + T_BL + b_off + pj*16*48);
        mma_pass(acc, Af, X);
#pragma unroll
        for (int ti = 0; ti < 2; ti++)
            ldsm_x4(X[ti], smb + buf + T_AL + a_off + ti*16*48);
        mma_pass(acc, X, Bf);

        if (more) {
            __syncthreads();
            const int nb = buf ^ BUFB;
            *(uint4*)(sm + nb + T_AH + stoff) = nA;
            *(uint4*)(sm + nb + T_AL + stoff) = nAl;
            *(uint4*)(sm + nb + T_BH + stoff) = nB;
            *(uint4*)(sm + nb + T_BL + stoff) = nBl;
            __syncthreads();
        }
    }

    const int rb = i0 + wm*32 + (lane >> 2);
    const int cb = j0 + wn*64 + (lane & 3) * 2;
#pragma unroll
    for (int ti = 0; ti < 2; ti++)
#pragma unroll
        for (int tj = 0; tj < 8; tj++) {
            const int i = rb + ti*16, j = cb + tj*8;
            uint32_t lo0, lo1;
            uint32_t hi0 = packhl(acc[ti][tj][0], acc[ti][tj][1], lo0);
            uint32_t hi1 = packhl(acc[ti][tj][2], acc[ti][tj][3], lo1);
            *(uint32_t*)&Ch[(size_t)i*N + j]     = hi0;
            *(uint32_t*)&Cl[(size_t)i*N + j]     = lo0;
            *(uint32_t*)&Ch[(size_t)(i+8)*N + j] = hi1;
            *(uint32_t*)&Cl[(size_t)(i+8)*N + j] = lo1;
        }
}

// ============================================================
// plain bf16 gemm (1 product): out-path tolerant (V proj, FC)
// ============================================================
__global__ __launch_bounds__(256, 2)
void gemm_plain(const bf16* __restrict__ Ah, const bf16* __restrict__ Bh,
                float* __restrict__ Cf, bf16* __restrict__ Ch,
                int N, int K)
{
    extern __shared__ __align__(128) char sm[];
    const uint32_t smb = smem_u32(sm);
    const int t = threadIdx.x;
    const int lane = t & 31, warp = t >> 5;
    const int wm = warp >> 1, wn = warp & 1;
    const int i0 = blockIdx.y * 128, j0 = blockIdx.x * 128;

    float acc[2][8][4];
#pragma unroll
    for (int a = 0; a < 2; a++)
#pragma unroll
        for (int b = 0; b < 8; b++)
#pragma unroll
            for (int c = 0; c < 4; c++) acc[a][b][c] = 0.f;

    const int r = t >> 1, kc = (t & 1) * 8;
    const int stoff = r * 48 + (t & 1) * 16;
    const bf16* pAh = Ah + (size_t)(i0 + r) * K + kc;
    const bf16* pBh = Bh + (size_t)(j0 + r) * K + kc;

    const uint32_t a_off = (uint32_t)((wm*32 + (lane & 15)) * 48 + ((lane >> 4) & 1) * 16);
    const uint32_t b_off = (uint32_t)((wn*64 + (lane & 7) + ((lane >> 4) & 1) * 8) * 48
                                      + ((lane >> 3) & 1) * 16);

    *(uint4*)(sm + stoff)        = *(const uint4*)pAh;
    *(uint4*)(sm + 6144 + stoff) = *(const uint4*)pBh;
    __syncthreads();

    const int nst = K / 16;
    for (int s = 0; s < nst; s++) {
        const int buf = (s & 1) * PBUF;
        const bool more = (s + 1 < nst);
        uint4 nA, nB;
        if (more) {
            nA = *(const uint4*)(pAh + (s+1)*16);
            nB = *(const uint4*)(pBh + (s+1)*16);
        }
        uint32_t Af[2][4], Bf[4][4];
#pragma unroll
        for (int ti = 0; ti < 2; ti++)
            ldsm_x4(Af[ti], smb + buf + a_off + ti*16*48);
#pragma unroll
        for (int pj = 0; pj < 4; pj++)
            ldsm_x4(Bf[pj], smb + buf + 6144 + b_off + pj*16*48);
        mma_pass(acc, Af, Bf);

        if (more) {
            __syncthreads();
            const int nb = buf ^ PBUF;
            *(uint4*)(sm + nb + stoff)        = nA;
            *(uint4*)(sm + nb + 6144 + stoff) = nB;
            __syncthreads();
        }
    }

    const int rb = i0 + wm*32 + (lane >> 2);
    const int cb = j0 + wn*64 + (lane & 3) * 2;
    if (Cf) {
#pragma unroll
        for (int ti = 0; ti < 2; ti++)
#pragma unroll
            for (int tj = 0; tj < 8; tj++) {
                const int i = rb + ti*16, j = cb + tj*8;
                *(float2*)&Cf[(size_t)i*N + j]     = make_float2(acc[ti][tj][0], acc[ti][tj][1]);
                *(float2*)&Cf[(size_t)(i+8)*N + j] = make_float2(acc[ti][tj][2], acc[ti][tj][3]);
            }
    } else {
#pragma unroll
        for (int ti = 0; ti < 2; ti++)
#pragma unroll
            for (int tj = 0; tj < 8; tj++) {
                const int i = rb + ti*16, j = cb + tj*8;
                *(uint32_t*)&Ch[(size_t)i*N + j]     = pack2(acc[ti][tj][0], acc[ti][tj][1]);
                *(uint32_t*)&Ch[(size_t)(i+8)*N + j] = pack2(acc[ti][tj][2], acc[ti][tj][3]);
            }
    }
}

// ============================================================
// fused flash attention: j-tile 64, 2 CTAs/SM, cp.async K/V staging.
// V plain bf16 in PV; P hi/lo; ctx out plain bf16.
// ============================================================
#define KST 144
#define FBUF 27648
#define FKH(b) ((b)*FBUF)
#define FKL(b) ((b)*FBUF + 9216)
#define FVH(b) ((b)*FBUF + 18432)
#define DYNSM_F 55296

__device__ __forceinline__ void stage_kv64_async(uint32_t smb, int hOff, int lOff,
                                                 const bf16* srcH, const bf16* srcL, int t)
{
    const int row = t >> 2, ch = t & 3;
    const size_t g = (size_t)row*DD + ch*16;
    const int so = row*KST + ch*32;
    cp16(smb + hOff + so,      srcH + g);
    cp16(smb + hOff + so + 16, srcH + g + 8);
    cp16(smb + lOff + so,      srcL + g);
    cp16(smb + lOff + so + 16, srcL + g + 8);
}
__device__ __forceinline__ void stage_v64_async(uint32_t smb, int hOff,
                                                const bf16* srcH, int t)
{
    const int row = t >> 2, ch = t & 3;
    const size_t g = (size_t)row*DD + ch*16;
    const int so = row*KST + ch*32;
    cp16(smb + hOff + so,      srcH + g);
    cp16(smb + hOff + so + 16, srcH + g + 8);
}
__device__ __forceinline__ void stage_q128_b(char* sm, int hOff, int lOff,
                                             const bf16* srcH, const bf16* srcL, int t)
{
    const int row = t >> 1, half = t & 1;
    const size_t g = (size_t)row*DD + half*32;
    const int so = row*KST + half*64;
#pragma unroll
    for (int q = 0; q < 4; q++) {
        *(uint4*)(sm + hOff + so + q*16) = *(const uint4*)(srcH + g + q*8);
        *(uint4*)(sm + lOff + so + q*16) = *(const uint4*)(srcL + g + q*8);
    }
}

__global__ __launch_bounds__(256, 2)
void flash_attn(const int* __restrict__ mask)
{
    extern __shared__ __align__(128) char sm[];
    const uint32_t smb = smem_u32(sm);
    const int t = threadIdx.x;
    const int lane = t & 31, w = t >> 5;
    const int rbk = blockIdx.x, bh = blockIdx.y;
    const int b = bh >> 4, h = bh & 15;
    const int i0 = rbk * 128;

    const size_t qoff = ((size_t)b*SS + i0)*DD + h*DK;
    const size_t koff = (size_t)b*SS*DD + h*DK;

    stage_q128_b(sm, 0, 18432, g_qh + qoff, g_ql + qoff, t);
    __syncthreads();

    uint32_t Qh[4][4], Ql[4][4];
    {
        const uint32_t a_base = (uint32_t)((w*16 + (lane & 15))*KST + ((lane >> 4) & 1)*16);
#pragma unroll
        for (int c = 0; c < 4; c++) {
            ldsm_x4(Qh[c], smb + a_base + c*32);
            ldsm_x4(Ql[c], smb + 18432 + a_base + c*32);
        }
    }
    __syncthreads();

    stage_kv64_async(smb, FKH(0), FKL(0), g_kh + koff, g_kl + koff, t);
    stage_v64_async(smb, FVH(0), g_vh + koff, t);
    cp_commit();
    cp_wait0();
    __syncthreads();

    float accO[8][4];
#pragma unroll
    for (int a = 0; a < 8; a++)
#pragma unroll
        for (int c = 0; c < 4; c++) accO[a][c] = 0.f;
    float lrun[2] = {0.f, 0.f};

    const int* mb = mask + (size_t)b*SS*SS;
    __half* prow = g_ph + (size_t)bh*SS*SS;
    const int r0l = w*16 + (lane >> 2);
    const int qrow = lane & 3;
    const int gi0 = i0 + r0l;

    const uint32_t kb_base = (uint32_t)(((lane & 7) + ((lane >> 4) & 1)*8)*KST
                                        + ((lane >> 3) & 1)*16);
    const uint32_t vb_base = (uint32_t)(((lane & 7) + ((lane >> 3) & 1)*8)*KST
                                        + ((lane >> 4) & 1)*16);

    for (int jt = 0; jt < 32; jt++) {
        const int buf = jt & 1;
        if (jt + 1 < 32) {
            const size_t nk = koff + (size_t)(jt+1)*64*DD;
            stage_kv64_async(smb, FKH(buf^1), FKL(buf^1), g_kh + nk, g_kl + nk, t);
            stage_v64_async(smb, FVH(buf^1), g_vh + nk, t);
            cp_commit();
        }

        // ---- S = Q K^T (3-product split) ----
        float accS[8][4];
#pragma unroll
        for (int a = 0; a < 8; a++)
#pragma unroll
            for (int c = 0; c < 4; c++) accS[a][c] = 0.f;
#pragma unroll
        for (int c = 0; c < 4; c++) {
#pragma unroll
            for (int jg = 0; jg < 4; jg++) {
                uint32_t Kh4[4], Kl4[4];
                const uint32_t ko = kb_base + (uint32_t)(jg*16*KST + c*32);
                ldsm_x4(Kh4, smb + FKH(buf) + ko);
                ldsm_x4(Kl4, smb + FKL(buf) + ko);
                mma_bf16(accS[2*jg],   Qh[c], Kh4);
                mma_bf16(accS[2*jg+1], Qh[c], Kh4 + 2);
                mma_bf16(accS[2*jg],   Ql[c], Kh4);
                mma_bf16(accS[2*jg+1], Ql[c], Kh4 + 2);
                mma_bf16(accS[2*jg],   Qh[c], Kl4);
                mma_bf16(accS[2*jg+1], Qh[c], Kl4 + 2);
            }
        }

        // ---- mask + scale + exp + row-sum ----
        float es0 = 0.f, es1 = 0.f;
#pragma unroll
        for (int tj = 0; tj < 8; tj++) {
            const int j = jt*64 + tj*8 + qrow*2;
            int2 m0 = *(const int2*)&mb[(size_t)gi0*SS + j];
            int2 m1 = *(const int2*)&mb[(size_t)(gi0+8)*SS + j];
            float e0 = m0.x ? 0.f : __expf(accS[tj][0]*0.125f);
            float e1 = m0.y ? 0.f : __expf(accS[tj][1]*0.125f);
            float e2 = m1.x ? 0.f : __expf(accS[tj][2]*0.125f);
            float e3 = m1.y ? 0.f : __expf(accS[tj][3]*0.125f);
            accS[tj][0] = e0; accS[tj][1] = e1;
            accS[tj][2] = e2; accS[tj][3] = e3;
            es0 += e0 + e1;
            es1 += e2 + e3;
        }
        es0 += __shfl_xor_sync(0xffffffffu, es0, 1);
        es0 += __shfl_xor_sync(0xffffffffu, es0, 2);
        es1 += __shfl_xor_sync(0xffffffffu, es1, 1);
        es1 += __shfl_xor_sync(0xffffffffu, es1, 2);
        lrun[0] += es0;
        lrun[1] += es1;

        // ---- write unnormalized P as fp16 (streaming stores) ----
#pragma unroll
        for (int tj = 0; tj < 8; tj++) {
            const int j = jt*64 + tj*8 + qrow*2;
            __half2 p0 = __floats2half2_rn(accS[tj][0], accS[tj][1]);
            __half2 p1 = __floats2half2_rn(accS[tj][2], accS[tj][3]);
            stg_cs_u32(&prow[(size_t)gi0*SS + j],     *(uint32_t*)&p0);
            stg_cs_u32(&prow[(size_t)(gi0+8)*SS + j], *(uint32_t*)&p1);
        }

        // ---- O += P @ V (P hi/lo x V bf16: 2 products) ----
#pragma unroll
        for (int q = 0; q < 4; q++) {
            uint32_t ah[4], al[4];
            ah[0] = packhl(accS[2*q][0],   accS[2*q][1],   al[0]);
            ah[1] = packhl(accS[2*q][2],   accS[2*q][3],   al[1]);
            ah[2] = packhl(accS[2*q+1][0], accS[2*q+1][1], al[2]);
            ah[3] = packhl(accS[2*q+1][2], accS[2*q+1][3], al[3]);
#pragma unroll
            for (int vg = 0; vg < 4; vg++) {
                uint32_t Vh4[4];
                const uint32_t vo = vb_base + (uint32_t)(q*16*KST + vg*32);
                ldsm_x4_t(Vh4, smb + FVH(buf) + vo);
                mma_bf16(accO[2*vg],   ah, Vh4);
                mma_bf16(accO[2*vg+1], ah, Vh4 + 2);
                mma_bf16(accO[2*vg],   al, Vh4);
                mma_bf16(accO[2*vg+1], al, Vh4 + 2);
            }
        }
        if (jt + 1 < 32) cp_wait0();
        __syncthreads();
    }

    // ---- finalize: row sums + ctx written as plain bf16 ----
    if ((lane & 3) == 0) {
        g_ls[(size_t)bh*SS + gi0]     = lrun[0];
        g_ls[(size_t)bh*SS + gi0 + 8] = lrun[1];
    }
    const float rl0 = 1.f / lrun[0];
    const float rl1 = 1.f / lrun[1];
    const size_t c0 = ((size_t)b*SS + gi0)*DD + h*DK + qrow*2;
#pragma unroll
    for (int nj = 0; nj < 8; nj++) {
        *(uint32_t*)&g_ch[c0 + nj*8]        = pack2(accO[nj][0]*rl0, accO[nj][1]*rl0);
        *(uint32_t*)&g_ch[c0 + 8*DD + nj*8] = pack2(accO[nj][2]*rl1, accO[nj][3]*rl1);
    }
}

// ============================================================
// attn normalization: attn = half(P) * (1/l)  -> fp32 out
// ============================================================
__global__ void fix_attn(float* __restrict__ attn)
{
    const int blk = blockIdx.x;
    const int bh = blk >> 11, row = blk & 2047;
    const float linv = 1.0f / g_ls[(size_t)bh*SS + row];
    const int t = threadIdx.x;
    const size_t base = ((size_t)bh*SS + row)*SS;
    uint4 raw = *(const uint4*)(g_ph + base + t*8);
    const __half2* hp = (const __half2*)&raw;
    float* dst = attn + base + t*8;
    float2 f0 = __half22float2(hp[0]);
    float2 f1 = __half22float2(hp[1]);
    float2 f2 = __half22float2(hp[2]);
    float2 f3 = __half22float2(hp[3]);
    float4 o0 = make_float4(f0.x*linv, f0.y*linv, f1.x*linv, f1.y*linv);
    float4 o1 = make_float4(f2.x*linv, f2.y*linv, f3.x*linv, f3.y*linv);
    *(float4*)(dst)     = o0;
    *(float4*)(dst + 4) = o1;
}

// ============================================================
// out = LayerNorm(pre + residual)
// ============================================================
__global__ void ln_kernel(const float* __restrict__ resid,
                          float* __restrict__ out)
{
    const size_t base = (size_t)blockIdx.x * DD;
    const int t = threadIdx.x;
    __shared__ float red1[8];
    __shared__ float red2[8];

    float v[4];
    float s = 0.f;
#pragma unroll
    for (int j = 0; j < 4; j++) {
        v[j] = g_pre[base + t + 256*j] + resid[base + t + 256*j];
        s += v[j];
    }
#pragma unroll
    for (int o = 16; o > 0; o >>= 1) s += __shfl_xor_sync(0xffffffffu, s, o);
    if ((t & 31) == 0) red1[t >> 5] = s;
    __syncthreads();
    s = red1[0];
#pragma unroll
    for (int w = 1; w < 8; w++) s += red1[w];
    const float mu = s * (1.0f / DD);

    float sq = 0.f;
#pragma unroll
    for (int j = 0; j < 4; j++) { const float d = v[j] - mu; sq += d*d; }
#pragma unroll
    for (int o = 16; o > 0; o >>= 1) sq += __shfl_xor_sync(0xffffffffu, sq, o);
    if ((t & 31) == 0) red2[t >> 5] = sq;
    __syncthreads();
    sq = red2[0];
#pragma unroll
    for (int w = 1; w < 8; w++) sq += red2[w];
    const float inv = rsqrtf(sq * (1.0f / DD) + 1e-5f);

#pragma unroll
    for (int j = 0; j < 4; j++) out[base + t + 256*j] = (v[j] - mu) * inv;
}

// ============================================================
extern "C" void kernel_launch(void* const* d_in, const int* in_sizes, int n_in,
                              void* d_out, int out_size)
{
    const float* inQ  = (const float*)d_in[0];
    const float* inK  = (const float*)d_in[1];
    const float* inV  = (const float*)d_in[2];
    const int*   mask = (const int*)  d_in[3];
    const float* WQ   = (const float*)d_in[4];
    const float* WK   = (const float*)d_in[5];
    const float* WV   = (const float*)d_in[6];
    const float* Wfc  = (const float*)d_in[7];
    float* out = (float*)d_out;

    bf16 *aqh, *aql, *akh, *akl, *avh;
    bf16 *wqh, *wql, *wkh, *wkl, *wvh, *wfh;
    bf16 *qh, *ql, *kh, *kl, *vh, *ch;
    float *ppre, *psc, *pdmy;
    cudaGetSymbolAddress((void**)&aqh, g_aqh); cudaGetSymbolAddress((void**)&aql, g_aql);
    cudaGetSymbolAddress((void**)&akh, g_akh); cudaGetSymbolAddress((void**)&akl, g_akl);
    cudaGetSymbolAddress((void**)&avh, g_avh);
    cudaGetSymbolAddress((void**)&wqh, g_wqh); cudaGetSymbolAddress((void**)&wql, g_wql);
    cudaGetSymbolAddress((void**)&wkh, g_wkh); cudaGetSymbolAddress((void**)&wkl, g_wkl);
    cudaGetSymbolAddress((void**)&wvh, g_wvh);
    cudaGetSymbolAddress((void**)&wfh, g_wfh);
    cudaGetSymbolAddress((void**)&qh, g_qh);   cudaGetSymbolAddress((void**)&ql, g_ql);
    cudaGetSymbolAddress((void**)&kh, g_kh);   cudaGetSymbolAddress((void**)&kl, g_kl);
    cudaGetSymbolAddress((void**)&vh, g_vh);
    cudaGetSymbolAddress((void**)&ch, g_ch);
    cudaGetSymbolAddress((void**)&ppre, g_pre);
    cudaGetSymbolAddress((void**)&psc,  g_scores);
    cudaGetSymbolAddress((void**)&pdmy, g_dummy_out);

    const long long OUT_E  = (long long)NT * DD;
    const long long ATTN_E = (long long)BB * HH * SS * SS;

    float* out_dst  = out;
    float* attn_dst = psc;
    if ((long long)out_size >= OUT_E + ATTN_E) {
        attn_dst = out + OUT_E;
    } else if ((long long)out_size == ATTN_E) {
        attn_dst = out;
        out_dst  = pdmy;
    }

    cudaFuncSetAttribute(flash_attn, cudaFuncAttributeMaxDynamicSharedMemorySize, DYNSM_F);

    const dim3 blk(256);
    const int NACT = NT*DD/1024;
    const int NW   = DD*DD/1024;

    // pre-split Q/K paths (hi/lo); plain convert for V and FC paths
    presplit<<<NACT, blk>>>((const float4*)inQ, (uint2*)aqh, (uint2*)aql);
    presplit<<<NACT, blk>>>((const float4*)inK, (uint2*)akh, (uint2*)akl);
    preconv<<<NACT, blk>>>((const float4*)inV, (uint2*)avh);
    presplit<<<NW,   blk>>>((const float4*)WQ,  (uint2*)wqh, (uint2*)wql);
    presplit<<<NW,   blk>>>((const float4*)WK,  (uint2*)wkh, (uint2*)wkl);
    preconv<<<NW,   blk>>>((const float4*)WV,  (uint2*)wvh);
    preconv<<<NW,   blk>>>((const float4*)Wfc, (uint2*)wfh);

    // Q/K projections: 3-product split (feed exp)
    gemm_mma_b<<<dim3(DD/128, NT/128), blk, DYNSM>>>(aqh, aql, wqh, wql, qh, ql, DD, DD);
    gemm_mma_b<<<dim3(DD/128, NT/128), blk, DYNSM>>>(akh, akl, wkh, wkl, kh, kl, DD, DD);
    // V projection: plain bf16 (out-path tolerant)
    gemm_plain<<<dim3(DD/128, NT/128), blk, DYNSM_P>>>(avh, wvh, nullptr, vh, DD, DD);

    // fused attention (cp.async staging; P -> fp16 scratch; V plain bf16)
    flash_attn<<<dim3(16, BB*HH), blk, DYNSM_F>>>(mask);

    // normalize: fp16 P -> fp32 attn
    fix_attn<<<(unsigned)(BB*HH*SS), blk>>>(attn_dst);

    // output projection: plain bf16 (out-path tolerant), fp32 out for LN
    gemm_plain<<<dim3(DD/128, NT/128), blk, DYNSM_P>>>(ch, wfh, ppre, nullptr, DD, DD);

    // residual + layernorm
    ln_kernel<<<(unsigned)NT, blk>>>(inQ, out_dst);
}